// round 12
// baseline (speedup 1.0000x reference)
#include <cuda_runtime.h>
#include <cuda_bf16.h>
#include <mma.h>
#include <math.h>

using namespace nvcuda;

#define NATOMS 25000
#define NEDGES 300000
#define NGRAPH 500
#define DDIM   256
#define ADIM   200
#define LLAYERS 3
#define TE     64      // rows per wmma block tile
#define NT     256     // threads per wmma block (8 warps: 4 M x 2 N)
#define LDA    264     // bf16 X row stride (528B, 16B-mult)
#define LDB    264     // bf16 B chunk row stride
#define SW_LD  20      // per-warp fp32 scratch row stride
#define KCH    16      // K chunk per step
#define NCH    (DDIM / KCH)

#define COEF_F ((float)(1.602176634e-19 * 1.602176634e-19 / \
                 (4.0 * 3.14159265358979323846 * 8.8541878128e-12 * 1e-10)))

typedef unsigned long long u64;

// smem layout (dynamic):
//   [0)        Xh[64*LDA] bf16, Xl[64*LDA] bf16       (67,584 B)
//   [SM_BOFF)  B stage0 (h+l), B stage1 (h+l)         (33,792 B)
//   [SM_SOFF)  per-warp fp32 scratch 8 x 16 x SW_LD   (10,240 B)
#define SM_XL   (64 * LDA)
#define SM_BOFF (2 * SM_XL * 2)                  // 67,584
#define SM_BSTG (2 * KCH * LDB * 2)              // 16,896 per stage (h+l)
#define SM_SOFF (SM_BOFF + 2 * SM_BSTG)          // 101,376
#define SMEM_W  (SM_SOFF + 8 * 16 * SW_LD * 4)   // 111,616 bytes

// ---- scratch (static device globals; no allocation) ----
__device__ float d_dist[NEDGES];
__device__ float d_h   [NATOMS * DDIM];
__device__ float d_hsrc[NATOMS * DDIM];
__device__ float d_hdst[NATOMS * DDIM];
__device__ float d_agg [NATOMS * DDIM];
__device__ float d_pool[NGRAPH];
__device__ int   d_cnt [NGRAPH];

// bf16-split weights, prepped once per launch. [L*4][256][256] row-major (k, n)
#define WELEMS (LLAYERS * 4 * DDIM * DDIM)
__device__ __align__(256) __nv_bfloat16 d_w1h[WELEMS];
__device__ __align__(256) __nv_bfloat16 d_w1l[WELEMS];
__device__ __align__(256) __nv_bfloat16 d_w2h[WELEMS];
__device__ __align__(256) __nv_bfloat16 d_w2l[WELEMS];

// ---- helpers ----
__device__ __forceinline__ void bsplit(float v, __nv_bfloat16& h, __nv_bfloat16& l) {
    h = __float2bfloat16(v);
    l = __float2bfloat16(v - __bfloat162float(h));
}
__device__ __forceinline__ void red2(float* p, float a, float b) {
    asm volatile("red.global.add.v2.f32 [%0], {%1, %2};" :: "l"(p), "f"(a), "f"(b) : "memory");
}
__device__ __forceinline__ float softplus_f(float x) {
    return fmaxf(x, 0.0f) + __logf(1.0f + __expf(-fabsf(x)));
}
__device__ __forceinline__ float mish_f(float x) {
    float ex = __expf(fminf(x, 20.0f));
    float p  = 1.0f + ex;
    float p2 = p * p;
    return x * __fdividef(p2 - 1.0f, p2 + 1.0f);
}

__device__ __forceinline__ void cpa16(unsigned saddr, const void* gptr) {
    asm volatile("cp.async.cg.shared.global [%0], [%1], 16;" :: "r"(saddr), "l"(gptr));
}
#define CP_COMMIT() asm volatile("cp.async.commit_group;" ::: "memory")
__device__ __forceinline__ void cp_wait0() { asm volatile("cp.async.wait_group 0;" ::: "memory"); }

// ---- weight prep: fp32 -> (hi, lo) bf16 split ----
__global__ void __launch_bounds__(256) prep_w(const float* __restrict__ cw1,
                                              const float* __restrict__ cw2) {
    int i = blockIdx.x * blockDim.x + threadIdx.x;
    if (i < WELEMS) {
        __nv_bfloat16 h, l;
        bsplit(cw1[i], h, l); d_w1h[i] = h; d_w1l[i] = l;
        bsplit(cw2[i], h, l); d_w2h[i] = h; d_w2l[i] = l;
    }
}

// ---- async B chunk load: 16 rows x 256 cols, h+l halves, 64B per thread ----
__device__ __forceinline__ void ldB_async(unsigned sB, const __nv_bfloat16* __restrict__ gWh,
                                          const __nv_bfloat16* __restrict__ gWl,
                                          int k0, int tid) {
    int rr = tid >> 4;             // 0..15
    int cb = (tid & 15) * 16;      // 0,16,..,240 (bf16 elems)
    unsigned dsth = sB + (unsigned)(rr * LDB + cb) * 2;
    unsigned dstl = dsth + KCH * LDB * 2;
    const __nv_bfloat16* sh = gWh + (size_t)(k0 + rr) * DDIM + cb;
    const __nv_bfloat16* sl = gWl + (size_t)(k0 + rr) * DDIM + cb;
    cpa16(dsth, sh);      cpa16(dsth + 16, sh + 8);
    cpa16(dstl, sl);      cpa16(dstl + 16, sl + 8);
}

// ---- single-sync pipelined wmma GEMM: D[64,256] = X @ W, 3-pass bf16 split ----
// Barrier at iter c simultaneously: publishes chunk c (after each thread's own
// cp_wait0) and proves all warps finished load_matrix reads of chunk c-1, so
// the buffer can be refilled. One barrier per chunk + one trailing (protects X
// and B from the caller's subsequent writes).
__device__ __forceinline__ void wgemm(
    const __nv_bfloat16* __restrict__ gWh, const __nv_bfloat16* __restrict__ gWl,
    const __nv_bfloat16* sXh, const __nv_bfloat16* sXl, char* smem,
    wmma::fragment<wmma::accumulator, 16, 16, 16, float>* acc,
    int tid, int mw, int nh) {
#pragma unroll
    for (int f = 0; f < 8; f++) wmma::fill_fragment(acc[f], 0.0f);
    __nv_bfloat16* sB0 = (__nv_bfloat16*)(smem + SM_BOFF);
    __nv_bfloat16* sB1 = (__nv_bfloat16*)(smem + SM_BOFF + SM_BSTG);
    unsigned a0 = (unsigned)__cvta_generic_to_shared(sB0);
    unsigned a1 = (unsigned)__cvta_generic_to_shared(sB1);
    ldB_async(a0, gWh, gWl, 0, tid);
    CP_COMMIT();
    for (int c = 0; c < NCH; c++) {
        cp_wait0();                    // my chunk-c copies done
        __syncthreads();               // chunk c visible; chunk c-1 reads complete
        if (c < NCH - 1) {
            ldB_async((c & 1) ? a0 : a1, gWh, gWl, (c + 1) * KCH, tid);
            CP_COMMIT();
        }
        const __nv_bfloat16* bh_base = (c & 1) ? sB1 : sB0;
        const __nv_bfloat16* bl_base = bh_base + KCH * LDB;
        wmma::fragment<wmma::matrix_a, 16, 16, 16, __nv_bfloat16, wmma::row_major> ah, al;
        wmma::load_matrix_sync(ah, sXh + mw * 16 * LDA + c * KCH, LDA);
        wmma::load_matrix_sync(al, sXl + mw * 16 * LDA + c * KCH, LDA);
#pragma unroll
        for (int f = 0; f < 8; f++) {
            wmma::fragment<wmma::matrix_b, 16, 16, 16, __nv_bfloat16, wmma::row_major> bh, bl;
            wmma::load_matrix_sync(bh, bh_base + nh * 128 + f * 16, LDB);
            wmma::load_matrix_sync(bl, bl_base + nh * 128 + f * 16, LDB);
            wmma::mma_sync(acc[f], ah, bh, acc[f]);
            wmma::mma_sync(acc[f], ah, bl, acc[f]);
            wmma::mma_sync(acc[f], al, bh, acc[f]);
        }
    }
    __syncthreads();                   // X/B free for caller writes
}

// ==== warp-local epilogues (no block barriers) ====
// Lane mapping per 16x16 frag: r = lane>>1 (0..15), c0 = (lane&1)*8.

// bias + mish -> X tile (bf16 split)
__device__ __forceinline__ void epi_mish_x(char* smem,
    wmma::fragment<wmma::accumulator, 16, 16, 16, float>* acc,
    const float* __restrict__ bias,
    __nv_bfloat16* sXh, __nv_bfloat16* sXl, int wid, int lane, int mw, int nh) {
    float* ws = (float*)(smem + SM_SOFF) + wid * 16 * SW_LD;
    int r = lane >> 1, c0 = (lane & 1) * 8;
    int R = mw * 16 + r;
#pragma unroll
    for (int f = 0; f < 8; f++) {
        wmma::store_matrix_sync(ws, acc[f], SW_LD, wmma::mem_row_major);
        __syncwarp();
        int C = nh * 128 + f * 16 + c0;
#pragma unroll
        for (int j = 0; j < 8; j++) {
            float v = mish_f(ws[r * SW_LD + c0 + j] + __ldg(bias + C + j));
            __nv_bfloat16 h, lo; bsplit(v, h, lo);
            sXh[R * LDA + C + j] = h; sXl[R * LDA + C + j] = lo;
        }
        __syncwarp();
    }
}

// bias -> global rows (guarded), float4 stores
__device__ __forceinline__ void epi_store_g(char* smem,
    wmma::fragment<wmma::accumulator, 16, 16, 16, float>* acc,
    const float* __restrict__ bias, float* __restrict__ g,
    int row0, int wid, int lane, int mw, int nh) {
    float* ws = (float*)(smem + SM_SOFF) + wid * 16 * SW_LD;
    int r = lane >> 1, c0 = (lane & 1) * 8;
    int row = row0 + mw * 16 + r;
#pragma unroll
    for (int f = 0; f < 8; f++) {
        wmma::store_matrix_sync(ws, acc[f], SW_LD, wmma::mem_row_major);
        __syncwarp();
        int C = nh * 128 + f * 16 + c0;
        if (row < NATOMS) {
            float4 o0, o1;
            o0.x = ws[r * SW_LD + c0 + 0] + __ldg(bias + C + 0);
            o0.y = ws[r * SW_LD + c0 + 1] + __ldg(bias + C + 1);
            o0.z = ws[r * SW_LD + c0 + 2] + __ldg(bias + C + 2);
            o0.w = ws[r * SW_LD + c0 + 3] + __ldg(bias + C + 3);
            o1.x = ws[r * SW_LD + c0 + 4] + __ldg(bias + C + 4);
            o1.y = ws[r * SW_LD + c0 + 5] + __ldg(bias + C + 5);
            o1.z = ws[r * SW_LD + c0 + 6] + __ldg(bias + C + 6);
            o1.w = ws[r * SW_LD + c0 + 7] + __ldg(bias + C + 7);
            *(float4*)(g + (size_t)row * DDIM + C)     = o0;
            *(float4*)(g + (size_t)row * DDIM + C + 4) = o1;
        }
        __syncwarp();
    }
}

// ---- small kernels ----
__global__ void __launch_bounds__(256) dist_kernel(const float* __restrict__ r) {
    int e = blockIdx.x * blockDim.x + threadIdx.x;
    if (e < NEDGES) {
        float x = r[3 * e], y = r[3 * e + 1], z = r[3 * e + 2];
        d_dist[e] = sqrtf(x * x + y * y + z * z);
    }
}

__global__ void __launch_bounds__(256) zero_pool_kernel() {
    int g = blockIdx.x * blockDim.x + threadIdx.x;
    if (g < NGRAPH) { d_pool[g] = 0.0f; d_cnt[g] = 0; }
}

__global__ void __launch_bounds__(256) pool_kernel(const int* __restrict__ gids,
                                                   const float* __restrict__ out_w) {
    int warp = (blockIdx.x * blockDim.x + threadIdx.x) >> 5;
    int lane = threadIdx.x & 31;
    if (warp >= NATOMS) return;
    float s = 0.0f;
    for (int k = lane; k < DDIM; k += 32) {
        size_t off = (size_t)warp * DDIM + k;
        s += softplus_f(d_h[off] + d_agg[off]) * out_w[k];
    }
#pragma unroll
    for (int off = 16; off > 0; off >>= 1)
        s += __shfl_xor_sync(0xFFFFFFFFu, s, off);
    if (lane == 0) {
        atomicAdd(&d_pool[gids[warp]], s);
        atomicAdd(&d_cnt[gids[warp]], 1);
    }
}

__global__ void __launch_bounds__(256) final_kernel(const float* __restrict__ out_b,
                                                    float* __restrict__ out) {
    int g = blockIdx.x * blockDim.x + threadIdx.x;
    if (g < NGRAPH)
        out[g] = d_pool[g] / fmaxf((float)d_cnt[g], 1.0f) + out_b[0];
}

// ==== scalar embed path (proven; off critical path) ====
#define ETE   32
#define ENT   128
#define EPADR 36
#define KEMB  224
__device__ __forceinline__ u64 pack2f(float lo, float hi) {
    u64 v; asm("mov.b64 %0, {%1, %2};" : "=l"(v) : "f"(lo), "f"(hi)); return v;
}
__device__ __forceinline__ void unpack2f(u64 v, float& lo, float& hi) {
    asm("mov.b64 {%0, %1}, %2;" : "=f"(lo), "=f"(hi) : "l"(v));
}
__device__ __forceinline__ void fma2(u64& a, u64 x, u64 w) {
    asm("fma.rn.f32x2 %0, %1, %2, %0;" : "+l"(a) : "l"(x), "l"(w));
}
__device__ __forceinline__ void eldw4c(float2 w[4][2], const float* __restrict__ W,
                                       int k, int cp, int kmax) {
#pragma unroll
    for (int i = 0; i < 4; i++) {
        int kk = k + i; if (kk >= kmax) kk = kmax - 1;
        w[i][0] = *(const float2*)(W + (size_t)kk * DDIM + 2 * cp);
        w[i][1] = *(const float2*)(W + (size_t)kk * DDIM + 2 * cp + 128);
    }
}
__device__ __forceinline__ void eldx(ulonglong2 cur[4], const float* __restrict__ xs, int k) {
    const ulonglong2* xr = (const ulonglong2*)(xs + (size_t)k * EPADR);
#pragma unroll
    for (int j = 0; j < 4; j++) cur[j] = xr[j];
}
__device__ __forceinline__ void efma_k(u64 acc[32], float2 w01, float2 w23,
                                       const ulonglong2 cur[4]) {
    u64 wv0 = pack2f(w01.x, w01.x), wv1 = pack2f(w01.y, w01.y);
    u64 wv2 = pack2f(w23.x, w23.x), wv3 = pack2f(w23.y, w23.y);
#pragma unroll
    for (int j2 = 0; j2 < 4; j2++) {
        u64 plo = cur[j2].x, phi = cur[j2].y;
        fma2(acc[     2 * j2], plo, wv0); fma2(acc[     2 * j2 + 1], phi, wv0);
        fma2(acc[ 8 + 2 * j2], plo, wv1); fma2(acc[ 8 + 2 * j2 + 1], phi, wv1);
        fma2(acc[16 + 2 * j2], plo, wv2); fma2(acc[16 + 2 * j2 + 1], phi, wv2);
        fma2(acc[24 + 2 * j2], plo, wv3); fma2(acc[24 + 2 * j2 + 1], phi, wv3);
    }
}
__global__ void __launch_bounds__(ENT) embed_kernel(const int* __restrict__ atom_types,
                                                    const float* __restrict__ af,
                                                    const float* __restrict__ emb_w,
                                                    const float* __restrict__ emb_b) {
    extern __shared__ float esm[];
    float* xa = esm;
    __shared__ int sT[ETE];
    int tid = threadIdx.x;
    int cp = tid & 63, rg = tid >> 6, rbase = rg * 16;
    int row0 = blockIdx.x * ETE;
    if (tid < ETE) {
        int row = row0 + tid;
        sT[tid] = (row < NATOMS) ? atom_types[row] : 0;
    }
    __syncthreads();
    for (int idx = tid; idx < ETE * KEMB; idx += ENT) {
        int r = idx / KEMB, k = idx - r * KEMB;
        float v = 0.0f;
        if (k < ADIM && row0 + r < NATOMS) v = af[(size_t)sT[r] * ADIM + k];
        xa[k * EPADR + r] = v;
    }
    __syncthreads();
    u64 acc[32];
#pragma unroll
    for (int j = 0; j < 32; j++) acc[j] = 0ULL;
    {
        const float* xs = xa + rbase;
        float2 wa[4][2], wb[4][2];
        ulonglong2 cur[4], nxt[4];
        eldw4c(wa, emb_w, 0, cp, ADIM);
        eldx(cur, xs, 0);
        for (int k0 = 0; k0 < KEMB; k0 += 8) {
            eldw4c(wb, emb_w, k0 + 4, cp, ADIM);
#pragma unroll
            for (int i = 0; i < 4; i++) {
                int kk = k0 + i + 1; if (kk >= KEMB) kk = 0;
                eldx(nxt, xs, kk);
                efma_k(acc, wa[i][0], wa[i][1], cur);
#pragma unroll
                for (int j = 0; j < 4; j++) cur[j] = nxt[j];
            }
            eldw4c(wa, emb_w, (k0 + 8 < KEMB) ? k0 + 8 : 0, cp, ADIM);
#pragma unroll
            for (int i = 0; i < 4; i++) {
                int kk = k0 + 5 + i; if (kk >= KEMB) kk = 0;
                eldx(nxt, xs, kk);
                efma_k(acc, wb[i][0], wb[i][1], cur);
#pragma unroll
                for (int j = 0; j < 4; j++) cur[j] = nxt[j];
            }
        }
    }
    float2 b01 = *(const float2*)(emb_b + 2 * cp);
    float2 b23 = *(const float2*)(emb_b + 2 * cp + 128);
#pragma unroll
    for (int j = 0; j < 8; j++) {
        float lo0, hi0, lo1, hi1, lo2, hi2, lo3, hi3;
        unpack2f(acc[j],      lo0, hi0);
        unpack2f(acc[8 + j],  lo1, hi1);
        unpack2f(acc[16 + j], lo2, hi2);
        unpack2f(acc[24 + j], lo3, hi3);
        int r0 = row0 + rbase + 2 * j, r1 = r0 + 1;
        if (r0 < NATOMS) {
            *(float2*)(d_h + (size_t)r0 * DDIM + 2 * cp)       = make_float2(lo0 + b01.x, lo1 + b01.y);
            *(float2*)(d_h + (size_t)r0 * DDIM + 2 * cp + 128) = make_float2(lo2 + b23.x, lo3 + b23.y);
        }
        if (r1 < NATOMS) {
            *(float2*)(d_h + (size_t)r1 * DDIM + 2 * cp)       = make_float2(hi0 + b01.x, hi1 + b01.y);
            *(float2*)(d_h + (size_t)r1 * DDIM + 2 * cp + 128) = make_float2(hi2 + b23.x, hi3 + b23.y);
        }
    }
}

// ==== wmma node kernel ====
__global__ void __launch_bounds__(NT, 2) node_kernel_w(
    int l, int use_agg, const float* __restrict__ cb1, const float* __restrict__ cb2) {
    extern __shared__ char smem[];
    __nv_bfloat16* sXh = (__nv_bfloat16*)smem;
    __nv_bfloat16* sXl = sXh + SM_XL;
    int tid = threadIdx.x, lane = tid & 31;
    int wid = tid >> 5, mw = wid & 3, nh = wid >> 2;
    int row0 = blockIdx.x * TE;

    const size_t MM = (size_t)DDIM * DDIM;
    const __nv_bfloat16 *w1sh = d_w1h + (size_t)(l * 4 + 0) * MM, *w1sl = d_w1l + (size_t)(l * 4 + 0) * MM;
    const __nv_bfloat16 *w2sh = d_w2h + (size_t)(l * 4 + 0) * MM, *w2sl = d_w2l + (size_t)(l * 4 + 0) * MM;
    const __nv_bfloat16 *w1dh = d_w1h + (size_t)(l * 4 + 1) * MM, *w1dl = d_w1l + (size_t)(l * 4 + 1) * MM;
    const __nv_bfloat16 *w2dh = d_w2h + (size_t)(l * 4 + 1) * MM, *w2dl = d_w2l + (size_t)(l * 4 + 1) * MM;
    const float *b1s = cb1 + (l * 4 + 0) * DDIM, *b2s = cb2 + (l * 4 + 0) * DDIM;
    const float *b1d = cb1 + (l * 4 + 1) * DDIM, *b2d = cb2 + (l * 4 + 1) * DDIM;

    // load h tile (+ fused softplus/agg-zero), split to bf16
    for (int i = tid; i < TE * DDIM; i += NT) {
        int r = i >> 8, c = i & 255;
        int row = row0 + r;
        float v = 0.0f;
        if (row < NATOMS) {
            size_t off = (size_t)row * DDIM + c;
            if (use_agg) { v = softplus_f(d_h[off] + d_agg[off]); d_h[off] = v; }
            else v = d_h[off];
            d_agg[off] = 0.0f;
        }
        __nv_bfloat16 h, lo; bsplit(v, h, lo);
        sXh[r * LDA + c] = h; sXl[r * LDA + c] = lo;
    }
    // (wgemm's first barrier publishes X)

    wmma::fragment<wmma::accumulator, 16, 16, 16, float> acc[8];

    // src branch
    wgemm(w1sh, w1sl, sXh, sXl, smem, acc, tid, mw, nh);
    epi_mish_x(smem, acc, b1s, sXh, sXl, wid, lane, mw, nh);
    wgemm(w2sh, w2sl, sXh, sXl, smem, acc, tid, mw, nh);
    epi_store_g(smem, acc, b2s, d_hsrc, row0, wid, lane, mw, nh);
    __syncthreads();  // all X reads done (wgemm trailing) + epilogue done before X rewrite

    // reload h for dst branch
    for (int i = tid; i < TE * DDIM; i += NT) {
        int r = i >> 8, c = i & 255;
        int row = row0 + r;
        float v = (row < NATOMS) ? d_h[(size_t)row * DDIM + c] : 0.0f;
        __nv_bfloat16 h, lo; bsplit(v, h, lo);
        sXh[r * LDA + c] = h; sXl[r * LDA + c] = lo;
    }
    wgemm(w1dh, w1dl, sXh, sXl, smem, acc, tid, mw, nh);
    epi_mish_x(smem, acc, b1d, sXh, sXl, wid, lane, mw, nh);
    wgemm(w2dh, w2dl, sXh, sXl, smem, acc, tid, mw, nh);
    epi_store_g(smem, acc, b2d, d_hdst, row0, wid, lane, mw, nh);
}

// ==== wmma edge kernel: RBF -> eMLP -> combine -> mMLP -> scatter ====
__global__ void __launch_bounds__(NT, 2) edge_kernel_w(
    const int* __restrict__ esrc, const int* __restrict__ edst, int l,
    const float* __restrict__ cb1, const float* __restrict__ cb2) {
    extern __shared__ char smem[];
    __nv_bfloat16* sXh = (__nv_bfloat16*)smem;
    __nv_bfloat16* sXl = sXh + SM_XL;
    __shared__ int   sS[TE], sD[TE];
    __shared__ float sDist[TE];
    int tid = threadIdx.x, lane = tid & 31;
    int wid = tid >> 5, mw = wid & 3, nh = wid >> 2;
    int e0 = blockIdx.x * TE;

    const size_t MM = (size_t)DDIM * DDIM;
    const __nv_bfloat16 *w1eh = d_w1h + (size_t)(l * 4 + 2) * MM, *w1el = d_w1l + (size_t)(l * 4 + 2) * MM;
    const __nv_bfloat16 *w2eh = d_w2h + (size_t)(l * 4 + 2) * MM, *w2el = d_w2l + (size_t)(l * 4 + 2) * MM;
    const __nv_bfloat16 *w1mh = d_w1h + (size_t)(l * 4 + 3) * MM, *w1ml = d_w1l + (size_t)(l * 4 + 3) * MM;
    const __nv_bfloat16 *w2mh = d_w2h + (size_t)(l * 4 + 3) * MM, *w2ml = d_w2l + (size_t)(l * 4 + 3) * MM;
    const float *b1e = cb1 + (l * 4 + 2) * DDIM, *b2e = cb2 + (l * 4 + 2) * DDIM;
    const float *b1m = cb1 + (l * 4 + 3) * DDIM, *b2m = cb2 + (l * 4 + 3) * DDIM;

    if (tid < TE) {
        int e = e0 + tid;
        sS[tid]    = (e < NEDGES) ? esrc[e] : 0;
        sD[tid]    = (e < NEDGES) ? edst[e] : 0;
        sDist[tid] = (e < NEDGES) ? d_dist[e] : 0.0f;
    }
    __syncthreads();

    // RBF -> X (bf16 split)
    for (int i = tid; i < TE * DDIM; i += NT) {
        int r = i >> 8, c = i & 255;
        float t = sDist[r] - (float)c * (1.0f / 255.0f);
        float v = __expf(-255.0f * t * t);
        __nv_bfloat16 h, lo; bsplit(v, h, lo);
        sXh[r * LDA + c] = h; sXl[r * LDA + c] = lo;
    }

    wmma::fragment<wmma::accumulator, 16, 16, 16, float> acc[8];
    float* ws = (float*)(smem + SM_SOFF) + wid * 16 * SW_LD;
    int r = lane >> 1, c0 = (lane & 1) * 8;
    int R = mw * 16 + r;

    // edge MLP layer 1: mish -> X
    wgemm(w1eh, w1el, sXh, sXl, smem, acc, tid, mw, nh);
    epi_mish_x(smem, acc, b1e, sXh, sXl, wid, lane, mw, nh);

    // edge MLP layer 2 + Coulomb combine -> X
    wgemm(w2eh, w2el, sXh, sXl, smem, acc, tid, mw, nh);
    {
        int s = sS[R], dd = sD[R];
#pragma unroll
        for (int f = 0; f < 8; f++) {
            wmma::store_matrix_sync(ws, acc[f], SW_LD, wmma::mem_row_major);
            __syncwarp();
            int C = nh * 128 + f * 16 + c0;
            float4 hs0 = *(const float4*)(d_hsrc + (size_t)s * DDIM + C);
            float4 hs1 = *(const float4*)(d_hsrc + (size_t)s * DDIM + C + 4);
            float4 hd0 = *(const float4*)(d_hdst + (size_t)dd * DDIM + C);
            float4 hd1 = *(const float4*)(d_hdst + (size_t)dd * DDIM + C + 4);
            float hs[8] = {hs0.x, hs0.y, hs0.z, hs0.w, hs1.x, hs1.y, hs1.z, hs1.w};
            float hd[8] = {hd0.x, hd0.y, hd0.z, hd0.w, hd1.x, hd1.y, hd1.z, hd1.w};
#pragma unroll
            for (int j = 0; j < 8; j++) {
                float el = ws[r * SW_LD + c0 + j] + __ldg(b2e + C + j);
                float v = __fdividef(hs[j] * hd[j] * COEF_F, el);
                __nv_bfloat16 h, lo; bsplit(v, h, lo);
                sXh[R * LDA + C + j] = h; sXl[R * LDA + C + j] = lo;
            }
            __syncwarp();
        }
    }

    // m MLP layer 1: mish -> X
    wgemm(w1mh, w1ml, sXh, sXl, smem, acc, tid, mw, nh);
    epi_mish_x(smem, acc, b1m, sXh, sXl, wid, lane, mw, nh);

    // m MLP layer 2 + segment-sum scatter
    wgemm(w2mh, w2ml, sXh, sXl, smem, acc, tid, mw, nh);
    {
        int dd = sD[R];
        bool ok = (e0 + R) < NEDGES;
#pragma unroll
        for (int f = 0; f < 8; f++) {
            wmma::store_matrix_sync(ws, acc[f], SW_LD, wmma::mem_row_major);
            __syncwarp();
            int C = nh * 128 + f * 16 + c0;
            if (ok) {
#pragma unroll
                for (int jj = 0; jj < 4; jj++) {
                    float v0 = ws[r * SW_LD + c0 + 2 * jj]     + __ldg(b2m + C + 2 * jj);
                    float v1 = ws[r * SW_LD + c0 + 2 * jj + 1] + __ldg(b2m + C + 2 * jj + 1);
                    red2(d_agg + (size_t)dd * DDIM + C + 2 * jj, v0, v1);
                }
            }
            __syncwarp();
        }
    }
}

extern "C" void kernel_launch(void* const* d_in, const int* in_sizes, int n_in,
                              void* d_out, int out_size) {
    const int*   atom_types = (const int*)  d_in[0];
    const int*   esrc       = (const int*)  d_in[1];
    const int*   edst       = (const int*)  d_in[2];
    const int*   gids       = (const int*)  d_in[3];
    const float* r          = (const float*)d_in[4];
    const float* af         = (const float*)d_in[5];
    const float* emb_w      = (const float*)d_in[6];
    const float* emb_b      = (const float*)d_in[7];
    const float* cw1        = (const float*)d_in[8];
    const float* cb1        = (const float*)d_in[9];
    const float* cw2        = (const float*)d_in[10];
    const float* cb2        = (const float*)d_in[11];
    const float* out_w      = (const float*)d_in[12];
    const float* out_b      = (const float*)d_in[13];
    float* out = (float*)d_out;

    const int SMEM_EMBED = KEMB * EPADR * 4;
    cudaFuncSetAttribute(edge_kernel_w, cudaFuncAttributeMaxDynamicSharedMemorySize, SMEM_W);
    cudaFuncSetAttribute(node_kernel_w, cudaFuncAttributeMaxDynamicSharedMemorySize, SMEM_W);
    cudaFuncSetAttribute(embed_kernel,  cudaFuncAttributeMaxDynamicSharedMemorySize, SMEM_EMBED);

    dist_kernel<<<(NEDGES + 255) / 256, 256>>>(r);
    prep_w<<<(WELEMS + 255) / 256, 256>>>(cw1, cw2);
    embed_kernel<<<(NATOMS + ETE - 1) / ETE, ENT, SMEM_EMBED>>>(atom_types, af, emb_w, emb_b);

    for (int l = 0; l < LLAYERS; l++) {
        node_kernel_w<<<(NATOMS + TE - 1) / TE, NT, SMEM_W>>>(l, l > 0 ? 1 : 0, cb1, cb2);
        edge_kernel_w<<<(NEDGES + TE - 1) / TE, NT, SMEM_W>>>(esrc, edst, l, cb1, cb2);
    }

    zero_pool_kernel<<<(NGRAPH + 255) / 256, 256>>>();
    pool_kernel<<<(NATOMS * 32 + 255) / 256, 256>>>(gids, out_w);
    final_kernel<<<(NGRAPH + 255) / 256, 256>>>(out_b, out);
}

// round 13
// speedup vs baseline: 1.2836x; 1.2836x over previous
#include <cuda_runtime.h>
#include <cuda_bf16.h>
#include <mma.h>
#include <math.h>

using namespace nvcuda;

#define NATOMS 25000
#define NEDGES 300000
#define NGRAPH 500
#define DDIM   256
#define ADIM   200
#define LLAYERS 3
#define TE     64      // rows per wmma block tile
#define NT     256     // threads per wmma block (8 warps: 2 M x 4 N)
#define LDA    264     // bf16 X row stride (528B, 16B-mult)
#define LDB    264     // bf16 B chunk row stride
#define LDF    132     // fp32 staging row stride (half = 128 cols + pad)
#define KCH    16      // K chunk per step
#define NCH    (DDIM / KCH)

#define COEF_F ((float)(1.602176634e-19 * 1.602176634e-19 / \
                 (4.0 * 3.14159265358979323846 * 8.8541878128e-12 * 1e-10)))

typedef unsigned long long u64;

// smem layout (dynamic):
//   [0)            Xh[64*LDA] bf16, Xl[64*LDA] bf16          (67,584 B)
//   [SM_BOFF)      B stage0 (h+l), B stage1 (h+l)            (33,792 B)
//                  -- aliased by F[64*LDF] fp32 during epilogues (33,776 B)
#define SM_XL   (64 * LDA)
#define SM_BOFF (2 * SM_XL * 2)             // 67,584 bytes
#define SM_BSTG (2 * KCH * LDB * 2)         // 16,896 bytes per stage (h+l)
#define SMEM_W  (SM_BOFF + 2 * SM_BSTG)     // 101,376 bytes

// ---- scratch (static device globals; no allocation) ----
__device__ float d_dist[NEDGES];
__device__ float d_h   [NATOMS * DDIM];
__device__ float d_hsrc[NATOMS * DDIM];
__device__ float d_hdst[NATOMS * DDIM];
__device__ float d_agg [NATOMS * DDIM];
__device__ float d_pool[NGRAPH];
__device__ int   d_cnt [NGRAPH];

// bf16-split weights, prepped once per launch. [L*4][256][256] row-major (k, n)
#define WELEMS (LLAYERS * 4 * DDIM * DDIM)
__device__ __align__(256) __nv_bfloat16 d_w1h[WELEMS];
__device__ __align__(256) __nv_bfloat16 d_w1l[WELEMS];
__device__ __align__(256) __nv_bfloat16 d_w2h[WELEMS];
__device__ __align__(256) __nv_bfloat16 d_w2l[WELEMS];

// ---- helpers ----
__device__ __forceinline__ void bsplit(float v, __nv_bfloat16& h, __nv_bfloat16& l) {
    h = __float2bfloat16(v);
    l = __float2bfloat16(v - __bfloat162float(h));
}
__device__ __forceinline__ void red2(float* p, float a, float b) {
    asm volatile("red.global.add.v2.f32 [%0], {%1, %2};" :: "l"(p), "f"(a), "f"(b) : "memory");
}
__device__ __forceinline__ float softplus_f(float x) {
    return fmaxf(x, 0.0f) + __logf(1.0f + __expf(-fabsf(x)));
}
__device__ __forceinline__ float mish_f(float x) {
    float ex = __expf(fminf(x, 20.0f));
    float p  = 1.0f + ex;
    float p2 = p * p;
    return x * __fdividef(p2 - 1.0f, p2 + 1.0f);
}

__device__ __forceinline__ void cpa16(unsigned saddr, const void* gptr) {
    asm volatile("cp.async.cg.shared.global [%0], [%1], 16;" :: "r"(saddr), "l"(gptr));
}
#define CP_COMMIT() asm volatile("cp.async.commit_group;" ::: "memory")
__device__ __forceinline__ void cp_wait1() { asm volatile("cp.async.wait_group 1;" ::: "memory"); }
__device__ __forceinline__ void cp_wait0() { asm volatile("cp.async.wait_group 0;" ::: "memory"); }

// ---- weight prep: fp32 -> (hi, lo) bf16 split ----
__global__ void __launch_bounds__(256) prep_w(const float* __restrict__ cw1,
                                              const float* __restrict__ cw2) {
    int i = blockIdx.x * blockDim.x + threadIdx.x;
    if (i < WELEMS) {
        __nv_bfloat16 h, l;
        bsplit(cw1[i], h, l); d_w1h[i] = h; d_w1l[i] = l;
        bsplit(cw2[i], h, l); d_w2h[i] = h; d_w2l[i] = l;
    }
}

// ---- async B chunk load: 16 rows x 256 cols, h+l halves, 64B per thread ----
__device__ __forceinline__ void ldB_async(unsigned sB, const __nv_bfloat16* __restrict__ gWh,
                                          const __nv_bfloat16* __restrict__ gWl,
                                          int k0, int tid) {
    int rr = tid >> 4;             // 0..15
    int cb = (tid & 15) * 16;      // 0,16,..,240 (bf16 elems)
    unsigned dsth = sB + (unsigned)(rr * LDB + cb) * 2;
    unsigned dstl = dsth + KCH * LDB * 2;
    const __nv_bfloat16* sh = gWh + (size_t)(k0 + rr) * DDIM + cb;
    const __nv_bfloat16* sl = gWl + (size_t)(k0 + rr) * DDIM + cb;
    cpa16(dsth, sh);      cpa16(dsth + 16, sh + 8);
    cpa16(dstl, sl);      cpa16(dstl + 16, sl + 8);
}

// ---- pipelined wmma GEMM: D[64,256] = X[64,256] @ W[256,256], 3-pass bf16 split ----
// Warp map: mw = wid>>2 (0..1) -> rows [mw*32, mw*32+32); nh = wid&3 (0..3) ->
// cols [nh*64, nh*64+64). acc[fm*4+fn] = frag (rows mw*32+fm*16, cols nh*64+fn*16).
// Per chunk per warp: 4 A-frag + 8 B-frag ldmatrix for 24 mma (LDSM halved vs 4Mx2N).
__device__ __forceinline__ void wgemm(
    const __nv_bfloat16* __restrict__ gWh, const __nv_bfloat16* __restrict__ gWl,
    const __nv_bfloat16* sXh, const __nv_bfloat16* sXl, char* smem,
    wmma::fragment<wmma::accumulator, 16, 16, 16, float>* acc,
    int tid, int mw, int nh) {
#pragma unroll
    for (int f = 0; f < 8; f++) wmma::fill_fragment(acc[f], 0.0f);
    __nv_bfloat16* sB0 = (__nv_bfloat16*)(smem + SM_BOFF);
    __nv_bfloat16* sB1 = (__nv_bfloat16*)(smem + SM_BOFF + SM_BSTG);
    unsigned a0 = (unsigned)__cvta_generic_to_shared(sB0);
    unsigned a1 = (unsigned)__cvta_generic_to_shared(sB1);
    ldB_async(a0, gWh, gWl, 0, tid);
    CP_COMMIT();
    for (int c = 0; c < NCH; c++) {
        __syncthreads();               // all warps done with the buffer we're about to refill
        if (c < NCH - 1) ldB_async((c & 1) ? a0 : a1, gWh, gWl, (c + 1) * KCH, tid);
        CP_COMMIT();
        if (c < NCH - 1) cp_wait1(); else cp_wait0();
        __syncthreads();               // chunk c visible to all warps
        const __nv_bfloat16* bh_base = (c & 1) ? sB1 : sB0;
        const __nv_bfloat16* bl_base = bh_base + KCH * LDB;
        wmma::fragment<wmma::matrix_a, 16, 16, 16, __nv_bfloat16, wmma::row_major> ah[2], al[2];
#pragma unroll
        for (int fm = 0; fm < 2; fm++) {
            wmma::load_matrix_sync(ah[fm], sXh + (mw * 32 + fm * 16) * LDA + c * KCH, LDA);
            wmma::load_matrix_sync(al[fm], sXl + (mw * 32 + fm * 16) * LDA + c * KCH, LDA);
        }
#pragma unroll
        for (int fn = 0; fn < 4; fn++) {
            wmma::fragment<wmma::matrix_b, 16, 16, 16, __nv_bfloat16, wmma::row_major> bh, bl;
            wmma::load_matrix_sync(bh, bh_base + nh * 64 + fn * 16, LDB);
            wmma::load_matrix_sync(bl, bl_base + nh * 64 + fn * 16, LDB);
#pragma unroll
            for (int fm = 0; fm < 2; fm++) {
                wmma::mma_sync(acc[fm * 4 + fn], ah[fm], bh, acc[fm * 4 + fn]);
                wmma::mma_sync(acc[fm * 4 + fn], ah[fm], bl, acc[fm * 4 + fn]);
                wmma::mma_sync(acc[fm * 4 + fn], al[fm], bh, acc[fm * 4 + fn]);
            }
        }
    }
    __syncthreads();                   // B dead; F may alias it now
}

// Stage one 128-col half into fp32 staging (aliases B region); returns sF.
// Warps with (nh>>1)==q own cols [q*128, q*128+128): local col = (nh&1)*64 + fn*16.
__device__ __forceinline__ float* stage_half(
    char* smem, wmma::fragment<wmma::accumulator, 16, 16, 16, float>* acc,
    int q, int mw, int nh) {
    float* sF = (float*)(smem + SM_BOFF);
    if ((nh >> 1) == q) {
#pragma unroll
        for (int fm = 0; fm < 2; fm++)
#pragma unroll
            for (int fn = 0; fn < 4; fn++)
                wmma::store_matrix_sync(sF + (mw * 32 + fm * 16) * LDF + (nh & 1) * 64 + fn * 16,
                                        acc[fm * 4 + fn], LDF, wmma::mem_row_major);
    }
    __syncthreads();
    return sF;
}

// ---- small kernels ----
__global__ void __launch_bounds__(256) dist_kernel(const float* __restrict__ r) {
    int e = blockIdx.x * blockDim.x + threadIdx.x;
    if (e < NEDGES) {
        float x = r[3 * e], y = r[3 * e + 1], z = r[3 * e + 2];
        d_dist[e] = sqrtf(x * x + y * y + z * z);
    }
}

__global__ void __launch_bounds__(256) zero_pool_kernel() {
    int g = blockIdx.x * blockDim.x + threadIdx.x;
    if (g < NGRAPH) { d_pool[g] = 0.0f; d_cnt[g] = 0; }
}

__global__ void __launch_bounds__(256) pool_kernel(const int* __restrict__ gids,
                                                   const float* __restrict__ out_w) {
    int warp = (blockIdx.x * blockDim.x + threadIdx.x) >> 5;
    int lane = threadIdx.x & 31;
    if (warp >= NATOMS) return;
    float s = 0.0f;
    for (int k = lane; k < DDIM; k += 32) {
        size_t off = (size_t)warp * DDIM + k;
        s += softplus_f(d_h[off] + d_agg[off]) * out_w[k];
    }
#pragma unroll
    for (int off = 16; off > 0; off >>= 1)
        s += __shfl_xor_sync(0xFFFFFFFFu, s, off);
    if (lane == 0) {
        atomicAdd(&d_pool[gids[warp]], s);
        atomicAdd(&d_cnt[gids[warp]], 1);
    }
}

__global__ void __launch_bounds__(256) final_kernel(const float* __restrict__ out_b,
                                                    float* __restrict__ out) {
    int g = blockIdx.x * blockDim.x + threadIdx.x;
    if (g < NGRAPH)
        out[g] = d_pool[g] / fmaxf((float)d_cnt[g], 1.0f) + out_b[0];
}

// ==== scalar embed path (proven; off critical path) ====
#define ETE   32
#define ENT   128
#define EPADR 36
#define KEMB  224
__device__ __forceinline__ u64 pack2f(float lo, float hi) {
    u64 v; asm("mov.b64 %0, {%1, %2};" : "=l"(v) : "f"(lo), "f"(hi)); return v;
}
__device__ __forceinline__ void unpack2f(u64 v, float& lo, float& hi) {
    asm("mov.b64 {%0, %1}, %2;" : "=f"(lo), "=f"(hi) : "l"(v));
}
__device__ __forceinline__ void fma2(u64& a, u64 x, u64 w) {
    asm("fma.rn.f32x2 %0, %1, %2, %0;" : "+l"(a) : "l"(x), "l"(w));
}
__device__ __forceinline__ void eldw4c(float2 w[4][2], const float* __restrict__ W,
                                       int k, int cp, int kmax) {
#pragma unroll
    for (int i = 0; i < 4; i++) {
        int kk = k + i; if (kk >= kmax) kk = kmax - 1;
        w[i][0] = *(const float2*)(W + (size_t)kk * DDIM + 2 * cp);
        w[i][1] = *(const float2*)(W + (size_t)kk * DDIM + 2 * cp + 128);
    }
}
__device__ __forceinline__ void eldx(ulonglong2 cur[4], const float* __restrict__ xs, int k) {
    const ulonglong2* xr = (const ulonglong2*)(xs + (size_t)k * EPADR);
#pragma unroll
    for (int j = 0; j < 4; j++) cur[j] = xr[j];
}
__device__ __forceinline__ void efma_k(u64 acc[32], float2 w01, float2 w23,
                                       const ulonglong2 cur[4]) {
    u64 wv0 = pack2f(w01.x, w01.x), wv1 = pack2f(w01.y, w01.y);
    u64 wv2 = pack2f(w23.x, w23.x), wv3 = pack2f(w23.y, w23.y);
#pragma unroll
    for (int j2 = 0; j2 < 4; j2++) {
        u64 plo = cur[j2].x, phi = cur[j2].y;
        fma2(acc[     2 * j2], plo, wv0); fma2(acc[     2 * j2 + 1], phi, wv0);
        fma2(acc[ 8 + 2 * j2], plo, wv1); fma2(acc[ 8 + 2 * j2 + 1], phi, wv1);
        fma2(acc[16 + 2 * j2], plo, wv2); fma2(acc[16 + 2 * j2 + 1], phi, wv2);
        fma2(acc[24 + 2 * j2], plo, wv3); fma2(acc[24 + 2 * j2 + 1], phi, wv3);
    }
}
__global__ void __launch_bounds__(ENT) embed_kernel(const int* __restrict__ atom_types,
                                                    const float* __restrict__ af,
                                                    const float* __restrict__ emb_w,
                                                    const float* __restrict__ emb_b) {
    extern __shared__ float esm[];
    float* xa = esm;
    __shared__ int sT[ETE];
    int tid = threadIdx.x;
    int cp = tid & 63, rg = tid >> 6, rbase = rg * 16;
    int row0 = blockIdx.x * ETE;
    if (tid < ETE) {
        int row = row0 + tid;
        sT[tid] = (row < NATOMS) ? atom_types[row] : 0;
    }
    __syncthreads();
    for (int idx = tid; idx < ETE * KEMB; idx += ENT) {
        int r = idx / KEMB, k = idx - r * KEMB;
        float v = 0.0f;
        if (k < ADIM && row0 + r < NATOMS) v = af[(size_t)sT[r] * ADIM + k];
        xa[k * EPADR + r] = v;
    }
    __syncthreads();
    u64 acc[32];
#pragma unroll
    for (int j = 0; j < 32; j++) acc[j] = 0ULL;
    {
        const float* xs = xa + rbase;
        float2 wa[4][2], wb[4][2];
        ulonglong2 cur[4], nxt[4];
        eldw4c(wa, emb_w, 0, cp, ADIM);
        eldx(cur, xs, 0);
        for (int k0 = 0; k0 < KEMB; k0 += 8) {
            eldw4c(wb, emb_w, k0 + 4, cp, ADIM);
#pragma unroll
            for (int i = 0; i < 4; i++) {
                int kk = k0 + i + 1; if (kk >= KEMB) kk = 0;
                eldx(nxt, xs, kk);
                efma_k(acc, wa[i][0], wa[i][1], cur);
#pragma unroll
                for (int j = 0; j < 4; j++) cur[j] = nxt[j];
            }
            eldw4c(wa, emb_w, (k0 + 8 < KEMB) ? k0 + 8 : 0, cp, ADIM);
#pragma unroll
            for (int i = 0; i < 4; i++) {
                int kk = k0 + 5 + i; if (kk >= KEMB) kk = 0;
                eldx(nxt, xs, kk);
                efma_k(acc, wb[i][0], wb[i][1], cur);
#pragma unroll
                for (int j = 0; j < 4; j++) cur[j] = nxt[j];
            }
        }
    }
    float2 b01 = *(const float2*)(emb_b + 2 * cp);
    float2 b23 = *(const float2*)(emb_b + 2 * cp + 128);
#pragma unroll
    for (int j = 0; j < 8; j++) {
        float lo0, hi0, lo1, hi1, lo2, hi2, lo3, hi3;
        unpack2f(acc[j],      lo0, hi0);
        unpack2f(acc[8 + j],  lo1, hi1);
        unpack2f(acc[16 + j], lo2, hi2);
        unpack2f(acc[24 + j], lo3, hi3);
        int r0 = row0 + rbase + 2 * j, r1 = r0 + 1;
        if (r0 < NATOMS) {
            *(float2*)(d_h + (size_t)r0 * DDIM + 2 * cp)       = make_float2(lo0 + b01.x, lo1 + b01.y);
            *(float2*)(d_h + (size_t)r0 * DDIM + 2 * cp + 128) = make_float2(lo2 + b23.x, lo3 + b23.y);
        }
        if (r1 < NATOMS) {
            *(float2*)(d_h + (size_t)r1 * DDIM + 2 * cp)       = make_float2(hi0 + b01.x, hi1 + b01.y);
            *(float2*)(d_h + (size_t)r1 * DDIM + 2 * cp + 128) = make_float2(hi2 + b23.x, hi3 + b23.y);
        }
    }
}

// ==== wmma node kernel ====
__global__ void __launch_bounds__(NT, 2) node_kernel_w(
    int l, int use_agg, const float* __restrict__ cb1, const float* __restrict__ cb2) {
    extern __shared__ char smem[];
    __nv_bfloat16* sXh = (__nv_bfloat16*)smem;
    __nv_bfloat16* sXl = sXh + SM_XL;
    int tid = threadIdx.x;
    int wid = tid >> 5, mw = wid >> 2, nh = wid & 3;
    int row0 = blockIdx.x * TE;

    const size_t MM = (size_t)DDIM * DDIM;
    const __nv_bfloat16 *w1sh = d_w1h + (size_t)(l * 4 + 0) * MM, *w1sl = d_w1l + (size_t)(l * 4 + 0) * MM;
    const __nv_bfloat16 *w2sh = d_w2h + (size_t)(l * 4 + 0) * MM, *w2sl = d_w2l + (size_t)(l * 4 + 0) * MM;
    const __nv_bfloat16 *w1dh = d_w1h + (size_t)(l * 4 + 1) * MM, *w1dl = d_w1l + (size_t)(l * 4 + 1) * MM;
    const __nv_bfloat16 *w2dh = d_w2h + (size_t)(l * 4 + 1) * MM, *w2dl = d_w2l + (size_t)(l * 4 + 1) * MM;
    const float *b1s = cb1 + (l * 4 + 0) * DDIM, *b2s = cb2 + (l * 4 + 0) * DDIM;
    const float *b1d = cb1 + (l * 4 + 1) * DDIM, *b2d = cb2 + (l * 4 + 1) * DDIM;

    // load h tile (+ fused softplus/agg-zero), split to bf16
    for (int i = tid; i < TE * DDIM; i += NT) {
        int r = i >> 8, c = i & 255;
        int row = row0 + r;
        float v = 0.0f;
        if (row < NATOMS) {
            size_t off = (size_t)row * DDIM + c;
            if (use_agg) { v = softplus_f(d_h[off] + d_agg[off]); d_h[off] = v; }
            else v = d_h[off];
            d_agg[off] = 0.0f;
        }
        __nv_bfloat16 h, lo; bsplit(v, h, lo);
        sXh[r * LDA + c] = h; sXl[r * LDA + c] = lo;
    }

    wmma::fragment<wmma::accumulator, 16, 16, 16, float> acc[8];

    // src branch
    wgemm(w1sh, w1sl, sXh, sXl, smem, acc, tid, mw, nh);
    for (int q = 0; q < 2; q++) {
        float* sF = stage_half(smem, acc, q, mw, nh);
        for (int i = tid; i < 64 * 128; i += NT) {
            int r = i >> 7, c = i & 127; int C = q * 128 + c;
            float v = mish_f(sF[r * LDF + c] + b1s[C]);
            __nv_bfloat16 h, lo; bsplit(v, h, lo);
            sXh[r * LDA + C] = h; sXl[r * LDA + C] = lo;
        }
        __syncthreads();
    }
    wgemm(w2sh, w2sl, sXh, sXl, smem, acc, tid, mw, nh);
    for (int q = 0; q < 2; q++) {
        float* sF = stage_half(smem, acc, q, mw, nh);
        for (int i = tid; i < 64 * 128; i += NT) {
            int r = i >> 7, c = i & 127; int C = q * 128 + c;
            int row = row0 + r;
            if (row < NATOMS) d_hsrc[(size_t)row * DDIM + C] = sF[r * LDF + c] + b2s[C];
        }
        __syncthreads();
    }

    // reload h for dst branch
    for (int i = tid; i < TE * DDIM; i += NT) {
        int r = i >> 8, c = i & 255;
        int row = row0 + r;
        float v = (row < NATOMS) ? d_h[(size_t)row * DDIM + c] : 0.0f;
        __nv_bfloat16 h, lo; bsplit(v, h, lo);
        sXh[r * LDA + c] = h; sXl[r * LDA + c] = lo;
    }
    wgemm(w1dh, w1dl, sXh, sXl, smem, acc, tid, mw, nh);
    for (int q = 0; q < 2; q++) {
        float* sF = stage_half(smem, acc, q, mw, nh);
        for (int i = tid; i < 64 * 128; i += NT) {
            int r = i >> 7, c = i & 127; int C = q * 128 + c;
            float v = mish_f(sF[r * LDF + c] + b1d[C]);
            __nv_bfloat16 h, lo; bsplit(v, h, lo);
            sXh[r * LDA + C] = h; sXl[r * LDA + C] = lo;
        }
        __syncthreads();
    }
    wgemm(w2dh, w2dl, sXh, sXl, smem, acc, tid, mw, nh);
    for (int q = 0; q < 2; q++) {
        float* sF = stage_half(smem, acc, q, mw, nh);
        for (int i = tid; i < 64 * 128; i += NT) {
            int r = i >> 7, c = i & 127; int C = q * 128 + c;
            int row = row0 + r;
            if (row < NATOMS) d_hdst[(size_t)row * DDIM + C] = sF[r * LDF + c] + b2d[C];
        }
        __syncthreads();
    }
}

// ==== wmma edge kernel: RBF -> eMLP -> combine -> mMLP -> scatter ====
__global__ void __launch_bounds__(NT, 2) edge_kernel_w(
    const int* __restrict__ esrc, const int* __restrict__ edst, int l,
    const float* __restrict__ cb1, const float* __restrict__ cb2) {
    extern __shared__ char smem[];
    __nv_bfloat16* sXh = (__nv_bfloat16*)smem;
    __nv_bfloat16* sXl = sXh + SM_XL;
    __shared__ int   sS[TE], sD[TE];
    __shared__ float sDist[TE];
    int tid = threadIdx.x;
    int wid = tid >> 5, mw = wid >> 2, nh = wid & 3;
    int e0 = blockIdx.x * TE;

    const size_t MM = (size_t)DDIM * DDIM;
    const __nv_bfloat16 *w1eh = d_w1h + (size_t)(l * 4 + 2) * MM, *w1el = d_w1l + (size_t)(l * 4 + 2) * MM;
    const __nv_bfloat16 *w2eh = d_w2h + (size_t)(l * 4 + 2) * MM, *w2el = d_w2l + (size_t)(l * 4 + 2) * MM;
    const __nv_bfloat16 *w1mh = d_w1h + (size_t)(l * 4 + 3) * MM, *w1ml = d_w1l + (size_t)(l * 4 + 3) * MM;
    const __nv_bfloat16 *w2mh = d_w2h + (size_t)(l * 4 + 3) * MM, *w2ml = d_w2l + (size_t)(l * 4 + 3) * MM;
    const float *b1e = cb1 + (l * 4 + 2) * DDIM, *b2e = cb2 + (l * 4 + 2) * DDIM;
    const float *b1m = cb1 + (l * 4 + 3) * DDIM, *b2m = cb2 + (l * 4 + 3) * DDIM;

    if (tid < TE) {
        int e = e0 + tid;
        sS[tid]    = (e < NEDGES) ? esrc[e] : 0;
        sD[tid]    = (e < NEDGES) ? edst[e] : 0;
        sDist[tid] = (e < NEDGES) ? d_dist[e] : 0.0f;
    }
    __syncthreads();

    // RBF -> X (bf16 split)
    for (int i = tid; i < TE * DDIM; i += NT) {
        int r = i >> 8, c = i & 255;
        float t = sDist[r] - (float)c * (1.0f / 255.0f);
        float v = __expf(-255.0f * t * t);
        __nv_bfloat16 h, lo; bsplit(v, h, lo);
        sXh[r * LDA + c] = h; sXl[r * LDA + c] = lo;
    }

    wmma::fragment<wmma::accumulator, 16, 16, 16, float> acc[8];

    // edge MLP layer 1: mish -> X
    wgemm(w1eh, w1el, sXh, sXl, smem, acc, tid, mw, nh);
    for (int q = 0; q < 2; q++) {
        float* sF = stage_half(smem, acc, q, mw, nh);
        for (int i = tid; i < 64 * 128; i += NT) {
            int r = i >> 7, c = i & 127; int C = q * 128 + c;
            float v = mish_f(sF[r * LDF + c] + b1e[C]);
            __nv_bfloat16 h, lo; bsplit(v, h, lo);
            sXh[r * LDA + C] = h; sXl[r * LDA + C] = lo;
        }
        __syncthreads();
    }

    // edge MLP layer 2 + Coulomb combine -> X
    wgemm(w2eh, w2el, sXh, sXl, smem, acc, tid, mw, nh);
    for (int q = 0; q < 2; q++) {
        float* sF = stage_half(smem, acc, q, mw, nh);
        for (int i = tid; i < 64 * 64; i += NT) {
            int r = i >> 6, c2 = i & 63; int C = q * 128 + 2 * c2;
            float el0 = sF[r * LDF + 2 * c2]     + b2e[C];
            float el1 = sF[r * LDF + 2 * c2 + 1] + b2e[C + 1];
            float2 hs = *(const float2*)(d_hsrc + (size_t)sS[r] * DDIM + C);
            float2 hd = *(const float2*)(d_hdst + (size_t)sD[r] * DDIM + C);
            float v0 = __fdividef(hs.x * hd.x * COEF_F, el0);
            float v1 = __fdividef(hs.y * hd.y * COEF_F, el1);
            __nv_bfloat16 h, lo;
            bsplit(v0, h, lo); sXh[r * LDA + C] = h;     sXl[r * LDA + C] = lo;
            bsplit(v1, h, lo); sXh[r * LDA + C + 1] = h; sXl[r * LDA + C + 1] = lo;
        }
        __syncthreads();
    }

    // m MLP layer 1: mish -> X
    wgemm(w1mh, w1ml, sXh, sXl, smem, acc, tid, mw, nh);
    for (int q = 0; q < 2; q++) {
        float* sF = stage_half(smem, acc, q, mw, nh);
        for (int i = tid; i < 64 * 128; i += NT) {
            int r = i >> 7, c = i & 127; int C = q * 128 + c;
            float v = mish_f(sF[r * LDF + c] + b1m[C]);
            __nv_bfloat16 h, lo; bsplit(v, h, lo);
            sXh[r * LDA + C] = h; sXl[r * LDA + C] = lo;
        }
        __syncthreads();
    }

    // m MLP layer 2 + segment-sum scatter
    wgemm(w2mh, w2ml, sXh, sXl, smem, acc, tid, mw, nh);
    for (int q = 0; q < 2; q++) {
        float* sF = stage_half(smem, acc, q, mw, nh);
        for (int i = tid; i < 64 * 64; i += NT) {
            int r = i >> 6, c2 = i & 63; int C = q * 128 + 2 * c2;
            if (e0 + r < NEDGES) {
                float v0 = sF[r * LDF + 2 * c2]     + b2m[C];
                float v1 = sF[r * LDF + 2 * c2 + 1] + b2m[C + 1];
                red2(d_agg + (size_t)sD[r] * DDIM + C, v0, v1);
            }
        }
        __syncthreads();
    }
}

extern "C" void kernel_launch(void* const* d_in, const int* in_sizes, int n_in,
                              void* d_out, int out_size) {
    const int*   atom_types = (const int*)  d_in[0];
    const int*   esrc       = (const int*)  d_in[1];
    const int*   edst       = (const int*)  d_in[2];
    const int*   gids       = (const int*)  d_in[3];
    const float* r          = (const float*)d_in[4];
    const float* af         = (const float*)d_in[5];
    const float* emb_w      = (const float*)d_in[6];
    const float* emb_b      = (const float*)d_in[7];
    const float* cw1        = (const float*)d_in[8];
    const float* cb1        = (const float*)d_in[9];
    const float* cw2        = (const float*)d_in[10];
    const float* cb2        = (const float*)d_in[11];
    const float* out_w      = (const float*)d_in[12];
    const float* out_b      = (const float*)d_in[13];
    float* out = (float*)d_out;

    const int SMEM_EMBED = KEMB * EPADR * 4;
    cudaFuncSetAttribute(edge_kernel_w, cudaFuncAttributeMaxDynamicSharedMemorySize, SMEM_W);
    cudaFuncSetAttribute(node_kernel_w, cudaFuncAttributeMaxDynamicSharedMemorySize, SMEM_W);
    cudaFuncSetAttribute(embed_kernel,  cudaFuncAttributeMaxDynamicSharedMemorySize, SMEM_EMBED);

    dist_kernel<<<(NEDGES + 255) / 256, 256>>>(r);
    prep_w<<<(WELEMS + 255) / 256, 256>>>(cw1, cw2);
    embed_kernel<<<(NATOMS + ETE - 1) / ETE, ENT, SMEM_EMBED>>>(atom_types, af, emb_w, emb_b);

    for (int l = 0; l < LLAYERS; l++) {
        node_kernel_w<<<(NATOMS + TE - 1) / TE, NT, SMEM_W>>>(l, l > 0 ? 1 : 0, cb1, cb2);
        edge_kernel_w<<<(NEDGES + TE - 1) / TE, NT, SMEM_W>>>(esrc, edst, l, cb1, cb2);
    }

    zero_pool_kernel<<<(NGRAPH + 255) / 256, 256>>>();
    pool_kernel<<<(NATOMS * 32 + 255) / 256, 256>>>(gids, out_w);
    final_kernel<<<(NGRAPH + 255) / 256, 256>>>(out_b, out);
}

// round 15
// speedup vs baseline: 1.9257x; 1.5002x over previous
#include <cuda_runtime.h>
#include <cuda_bf16.h>
#include <mma.h>
#include <math.h>

using namespace nvcuda;

#define NATOMS 25000
#define NEDGES 300000
#define NGRAPH 500
#define DDIM   256
#define ADIM   200
#define LLAYERS 3
#define TE     64
#define NT     256
#define LDA    264
#define LDB    264
#define LDF    132
#define KCH    16
#define NCH    (DDIM / KCH)
// e_lin interpolation table
#define ELIN_N    8192
#define ELIN_MAXD 2.0f

#define COEF_F ((float)(1.602176634e-19 * 1.602176634e-19 / \
                 (4.0 * 3.14159265358979323846 * 8.8541878128e-12 * 1e-10)))

typedef unsigned long long u64;

#define SM_XL   (64 * LDA)
#define SM_BOFF (2 * SM_XL * 2)
#define SM_BSTG (2 * KCH * LDB * 2)
#define SMEM_W  (SM_BOFF + 2 * SM_BSTG)     // 101,376 bytes

// ---- scratch ----
__device__ float d_dist[NEDGES];
__device__ float d_h   [NATOMS * DDIM];
__device__ float d_hsrc[NATOMS * DDIM];
__device__ float d_hdst[NATOMS * DDIM];
__device__ float d_agg [NATOMS * DDIM];
__device__ float d_pool[NGRAPH];
__device__ int   d_cnt [NGRAPH];
__device__ float d_elin[LLAYERS * ELIN_N * DDIM];   // e_lin lookup tables

#define WELEMS (LLAYERS * 4 * DDIM * DDIM)
__device__ __align__(256) __nv_bfloat16 d_w1h[WELEMS];
__device__ __align__(256) __nv_bfloat16 d_w1l[WELEMS];
__device__ __align__(256) __nv_bfloat16 d_w2h[WELEMS];
__device__ __align__(256) __nv_bfloat16 d_w2l[WELEMS];

// ---- helpers ----
__device__ __forceinline__ void bsplit(float v, __nv_bfloat16& h, __nv_bfloat16& l) {
    h = __float2bfloat16(v);
    l = __float2bfloat16(v - __bfloat162float(h));
}
__device__ __forceinline__ void red2(float* p, float a, float b) {
    asm volatile("red.global.add.v2.f32 [%0], {%1, %2};" :: "l"(p), "f"(a), "f"(b) : "memory");
}
__device__ __forceinline__ float softplus_f(float x) {
    return fmaxf(x, 0.0f) + __logf(1.0f + __expf(-fabsf(x)));
}
__device__ __forceinline__ float mish_f(float x) {
    float ex = __expf(fminf(x, 20.0f));
    float p  = 1.0f + ex;
    float p2 = p * p;
    return x * __fdividef(p2 - 1.0f, p2 + 1.0f);
}
__device__ __forceinline__ void cpa16(unsigned saddr, const void* gptr) {
    asm volatile("cp.async.cg.shared.global [%0], [%1], 16;" :: "r"(saddr), "l"(gptr));
}
#define CP_COMMIT() asm volatile("cp.async.commit_group;" ::: "memory")
__device__ __forceinline__ void cp_wait1() { asm volatile("cp.async.wait_group 1;" ::: "memory"); }
__device__ __forceinline__ void cp_wait0() { asm volatile("cp.async.wait_group 0;" ::: "memory"); }

// ---- weight prep ----
__global__ void __launch_bounds__(256) prep_w(const float* __restrict__ cw1,
                                              const float* __restrict__ cw2) {
    int i = blockIdx.x * blockDim.x + threadIdx.x;
    if (i < WELEMS) {
        __nv_bfloat16 h, l;
        bsplit(cw1[i], h, l); d_w1h[i] = h; d_w1l[i] = l;
        bsplit(cw2[i], h, l); d_w2h[i] = h; d_w2l[i] = l;
    }
}

// ---- wmma GEMM machinery (R13, 2M x 4N warp map) ----
__device__ __forceinline__ void ldB_async(unsigned sB, const __nv_bfloat16* __restrict__ gWh,
                                          const __nv_bfloat16* __restrict__ gWl,
                                          int k0, int tid) {
    int rr = tid >> 4;
    int cb = (tid & 15) * 16;
    unsigned dsth = sB + (unsigned)(rr * LDB + cb) * 2;
    unsigned dstl = dsth + KCH * LDB * 2;
    const __nv_bfloat16* sh = gWh + (size_t)(k0 + rr) * DDIM + cb;
    const __nv_bfloat16* sl = gWl + (size_t)(k0 + rr) * DDIM + cb;
    cpa16(dsth, sh);      cpa16(dsth + 16, sh + 8);
    cpa16(dstl, sl);      cpa16(dstl + 16, sl + 8);
}
__device__ __forceinline__ void wgemm(
    const __nv_bfloat16* __restrict__ gWh, const __nv_bfloat16* __restrict__ gWl,
    const __nv_bfloat16* sXh, const __nv_bfloat16* sXl, char* smem,
    wmma::fragment<wmma::accumulator, 16, 16, 16, float>* acc,
    int tid, int mw, int nh) {
#pragma unroll
    for (int f = 0; f < 8; f++) wmma::fill_fragment(acc[f], 0.0f);
    __nv_bfloat16* sB0 = (__nv_bfloat16*)(smem + SM_BOFF);
    __nv_bfloat16* sB1 = (__nv_bfloat16*)(smem + SM_BOFF + SM_BSTG);
    unsigned a0 = (unsigned)__cvta_generic_to_shared(sB0);
    unsigned a1 = (unsigned)__cvta_generic_to_shared(sB1);
    ldB_async(a0, gWh, gWl, 0, tid);
    CP_COMMIT();
    for (int c = 0; c < NCH; c++) {
        __syncthreads();
        if (c < NCH - 1) ldB_async((c & 1) ? a0 : a1, gWh, gWl, (c + 1) * KCH, tid);
        CP_COMMIT();
        if (c < NCH - 1) cp_wait1(); else cp_wait0();
        __syncthreads();
        const __nv_bfloat16* bh_base = (c & 1) ? sB1 : sB0;
        const __nv_bfloat16* bl_base = bh_base + KCH * LDB;
        wmma::fragment<wmma::matrix_a, 16, 16, 16, __nv_bfloat16, wmma::row_major> ah[2], al[2];
#pragma unroll
        for (int fm = 0; fm < 2; fm++) {
            wmma::load_matrix_sync(ah[fm], sXh + (mw * 32 + fm * 16) * LDA + c * KCH, LDA);
            wmma::load_matrix_sync(al[fm], sXl + (mw * 32 + fm * 16) * LDA + c * KCH, LDA);
        }
#pragma unroll
        for (int fn = 0; fn < 4; fn++) {
            wmma::fragment<wmma::matrix_b, 16, 16, 16, __nv_bfloat16, wmma::row_major> bh, bl;
            wmma::load_matrix_sync(bh, bh_base + nh * 64 + fn * 16, LDB);
            wmma::load_matrix_sync(bl, bl_base + nh * 64 + fn * 16, LDB);
#pragma unroll
            for (int fm = 0; fm < 2; fm++) {
                wmma::mma_sync(acc[fm * 4 + fn], ah[fm], bh, acc[fm * 4 + fn]);
                wmma::mma_sync(acc[fm * 4 + fn], ah[fm], bl, acc[fm * 4 + fn]);
                wmma::mma_sync(acc[fm * 4 + fn], al[fm], bh, acc[fm * 4 + fn]);
            }
        }
    }
    __syncthreads();
}
__device__ __forceinline__ float* stage_half(
    char* smem, wmma::fragment<wmma::accumulator, 16, 16, 16, float>* acc,
    int q, int mw, int nh) {
    float* sF = (float*)(smem + SM_BOFF);
    if ((nh >> 1) == q) {
#pragma unroll
        for (int fm = 0; fm < 2; fm++)
#pragma unroll
            for (int fn = 0; fn < 4; fn++)
                wmma::store_matrix_sync(sF + (mw * 32 + fm * 16) * LDF + (nh & 1) * 64 + fn * 16,
                                        acc[fm * 4 + fn], LDF, wmma::mem_row_major);
    }
    __syncthreads();
    return sF;
}

// ---- small kernels ----
__global__ void __launch_bounds__(256) dist_kernel(const float* __restrict__ r) {
    int e = blockIdx.x * blockDim.x + threadIdx.x;
    if (e < NEDGES) {
        float x = r[3 * e], y = r[3 * e + 1], z = r[3 * e + 2];
        d_dist[e] = sqrtf(x * x + y * y + z * z);
    }
}
__global__ void __launch_bounds__(256) zero_pool_kernel() {
    int g = blockIdx.x * blockDim.x + threadIdx.x;
    if (g < NGRAPH) { d_pool[g] = 0.0f; d_cnt[g] = 0; }
}
__global__ void __launch_bounds__(256) pool_kernel(const int* __restrict__ gids,
                                                   const float* __restrict__ out_w) {
    int warp = (blockIdx.x * blockDim.x + threadIdx.x) >> 5;
    int lane = threadIdx.x & 31;
    if (warp >= NATOMS) return;
    float s = 0.0f;
    for (int k = lane; k < DDIM; k += 32) {
        size_t off = (size_t)warp * DDIM + k;
        s += softplus_f(d_h[off] + d_agg[off]) * out_w[k];
    }
#pragma unroll
    for (int off = 16; off > 0; off >>= 1)
        s += __shfl_xor_sync(0xFFFFFFFFu, s, off);
    if (lane == 0) {
        atomicAdd(&d_pool[gids[warp]], s);
        atomicAdd(&d_cnt[gids[warp]], 1);
    }
}
__global__ void __launch_bounds__(256) final_kernel(const float* __restrict__ out_b,
                                                    float* __restrict__ out) {
    int g = blockIdx.x * blockDim.x + threadIdx.x;
    if (g < NGRAPH)
        out[g] = d_pool[g] / fmaxf((float)d_cnt[g], 1.0f) + out_b[0];
}

// ==== scalar embed (unchanged) ====
#define ETE   32
#define ENT   128
#define EPADR 36
#define KEMB  224
__device__ __forceinline__ u64 pack2f(float lo, float hi) {
    u64 v; asm("mov.b64 %0, {%1, %2};" : "=l"(v) : "f"(lo), "f"(hi)); return v;
}
__device__ __forceinline__ void unpack2f(u64 v, float& lo, float& hi) {
    asm("mov.b64 {%0, %1}, %2;" : "=f"(lo), "=f"(hi) : "l"(v));
}
__device__ __forceinline__ void fma2(u64& a, u64 x, u64 w) {
    asm("fma.rn.f32x2 %0, %1, %2, %0;" : "+l"(a) : "l"(x), "l"(w));
}
__device__ __forceinline__ void eldw4c(float2 w[4][2], const float* __restrict__ W,
                                       int k, int cp, int kmax) {
#pragma unroll
    for (int i = 0; i < 4; i++) {
        int kk = k + i; if (kk >= kmax) kk = kmax - 1;
        w[i][0] = *(const float2*)(W + (size_t)kk * DDIM + 2 * cp);
        w[i][1] = *(const float2*)(W + (size_t)kk * DDIM + 2 * cp + 128);
    }
}
__device__ __forceinline__ void eldx(ulonglong2 cur[4], const float* __restrict__ xs, int k) {
    const ulonglong2* xr = (const ulonglong2*)(xs + (size_t)k * EPADR);
#pragma unroll
    for (int j = 0; j < 4; j++) cur[j] = xr[j];
}
__device__ __forceinline__ void efma_k(u64 acc[32], float2 w01, float2 w23,
                                       const ulonglong2 cur[4]) {
    u64 wv0 = pack2f(w01.x, w01.x), wv1 = pack2f(w01.y, w01.y);
    u64 wv2 = pack2f(w23.x, w23.x), wv3 = pack2f(w23.y, w23.y);
#pragma unroll
    for (int j2 = 0; j2 < 4; j2++) {
        u64 plo = cur[j2].x, phi = cur[j2].y;
        fma2(acc[     2 * j2], plo, wv0); fma2(acc[     2 * j2 + 1], phi, wv0);
        fma2(acc[ 8 + 2 * j2], plo, wv1); fma2(acc[ 8 + 2 * j2 + 1], phi, wv1);
        fma2(acc[16 + 2 * j2], plo, wv2); fma2(acc[16 + 2 * j2 + 1], phi, wv2);
        fma2(acc[24 + 2 * j2], plo, wv3); fma2(acc[24 + 2 * j2 + 1], phi, wv3);
    }
}
__global__ void __launch_bounds__(ENT) embed_kernel(const int* __restrict__ atom_types,
                                                    const float* __restrict__ af,
                                                    const float* __restrict__ emb_w,
                                                    const float* __restrict__ emb_b) {
    extern __shared__ float esm[];
    float* xa = esm;
    __shared__ int sT[ETE];
    int tid = threadIdx.x;
    int cp = tid & 63, rg = tid >> 6, rbase = rg * 16;
    int row0 = blockIdx.x * ETE;
    if (tid < ETE) {
        int row = row0 + tid;
        sT[tid] = (row < NATOMS) ? atom_types[row] : 0;
    }
    __syncthreads();
    for (int idx = tid; idx < ETE * KEMB; idx += ENT) {
        int r = idx / KEMB, k = idx - r * KEMB;
        float v = 0.0f;
        if (k < ADIM && row0 + r < NATOMS) v = af[(size_t)sT[r] * ADIM + k];
        xa[k * EPADR + r] = v;
    }
    __syncthreads();
    u64 acc[32];
#pragma unroll
    for (int j = 0; j < 32; j++) acc[j] = 0ULL;
    {
        const float* xs = xa + rbase;
        float2 wa[4][2], wb[4][2];
        ulonglong2 cur[4], nxt[4];
        eldw4c(wa, emb_w, 0, cp, ADIM);
        eldx(cur, xs, 0);
        for (int k0 = 0; k0 < KEMB; k0 += 8) {
            eldw4c(wb, emb_w, k0 + 4, cp, ADIM);
#pragma unroll
            for (int i = 0; i < 4; i++) {
                int kk = k0 + i + 1; if (kk >= KEMB) kk = 0;
                eldx(nxt, xs, kk);
                efma_k(acc, wa[i][0], wa[i][1], cur);
#pragma unroll
                for (int j = 0; j < 4; j++) cur[j] = nxt[j];
            }
            eldw4c(wa, emb_w, (k0 + 8 < KEMB) ? k0 + 8 : 0, cp, ADIM);
#pragma unroll
            for (int i = 0; i < 4; i++) {
                int kk = k0 + 5 + i; if (kk >= KEMB) kk = 0;
                eldx(nxt, xs, kk);
                efma_k(acc, wb[i][0], wb[i][1], cur);
#pragma unroll
                for (int j = 0; j < 4; j++) cur[j] = nxt[j];
            }
        }
    }
    float2 b01 = *(const float2*)(emb_b + 2 * cp);
    float2 b23 = *(const float2*)(emb_b + 2 * cp + 128);
#pragma unroll
    for (int j = 0; j < 8; j++) {
        float lo0, hi0, lo1, hi1, lo2, hi2, lo3, hi3;
        unpack2f(acc[j],      lo0, hi0);
        unpack2f(acc[8 + j],  lo1, hi1);
        unpack2f(acc[16 + j], lo2, hi2);
        unpack2f(acc[24 + j], lo3, hi3);
        int r0 = row0 + rbase + 2 * j, r1 = r0 + 1;
        if (r0 < NATOMS) {
            *(float2*)(d_h + (size_t)r0 * DDIM + 2 * cp)       = make_float2(lo0 + b01.x, lo1 + b01.y);
            *(float2*)(d_h + (size_t)r0 * DDIM + 2 * cp + 128) = make_float2(lo2 + b23.x, lo3 + b23.y);
        }
        if (r1 < NATOMS) {
            *(float2*)(d_h + (size_t)r1 * DDIM + 2 * cp)       = make_float2(hi0 + b01.x, hi1 + b01.y);
            *(float2*)(d_h + (size_t)r1 * DDIM + 2 * cp + 128) = make_float2(hi2 + b23.x, hi3 + b23.y);
        }
    }
}

// ==== e_lin table build: d_elin[l][row] = mlp(rbf(d_row)) for grid d over [0, ELIN_MAXD] ====
__global__ void __launch_bounds__(NT, 2) elin_kernel(
    int l, const float* __restrict__ cb1, const float* __restrict__ cb2) {
    extern __shared__ char smem[];
    __nv_bfloat16* sXh = (__nv_bfloat16*)smem;
    __nv_bfloat16* sXl = sXh + SM_XL;
    int tid = threadIdx.x;
    int wid = tid >> 5, mw = wid >> 2, nh = wid & 3;
    int row0 = blockIdx.x * TE;
    const size_t MM = (size_t)DDIM * DDIM;
    const __nv_bfloat16 *w1h = d_w1h + (size_t)(l * 4 + 2) * MM, *w1l = d_w1l + (size_t)(l * 4 + 2) * MM;
    const __nv_bfloat16 *w2h = d_w2h + (size_t)(l * 4 + 2) * MM, *w2l = d_w2l + (size_t)(l * 4 + 2) * MM;
    const float *b1 = cb1 + (l * 4 + 2) * DDIM, *b2 = cb2 + (l * 4 + 2) * DDIM;
    const float step = ELIN_MAXD / (float)(ELIN_N - 1);

    for (int i = tid; i < TE * DDIM; i += NT) {
        int r = i >> 8, c = i & 255;
        float d = (float)(row0 + r) * step;
        float t = d - (float)c * (1.0f / 255.0f);
        float v = __expf(-255.0f * t * t);
        __nv_bfloat16 h, lo; bsplit(v, h, lo);
        sXh[r * LDA + c] = h; sXl[r * LDA + c] = lo;
    }
    wmma::fragment<wmma::accumulator, 16, 16, 16, float> acc[8];
    wgemm(w1h, w1l, sXh, sXl, smem, acc, tid, mw, nh);
    for (int q = 0; q < 2; q++) {
        float* sF = stage_half(smem, acc, q, mw, nh);
        for (int i = tid; i < 64 * 128; i += NT) {
            int r = i >> 7, c = i & 127; int C = q * 128 + c;
            float v = mish_f(sF[r * LDF + c] + b1[C]);
            __nv_bfloat16 h, lo; bsplit(v, h, lo);
            sXh[r * LDA + C] = h; sXl[r * LDA + C] = lo;
        }
        __syncthreads();
    }
    wgemm(w2h, w2l, sXh, sXl, smem, acc, tid, mw, nh);
    float* out = d_elin + (size_t)l * ELIN_N * DDIM;
    for (int q = 0; q < 2; q++) {
        float* sF = stage_half(smem, acc, q, mw, nh);
        for (int i = tid; i < 64 * 128; i += NT) {
            int r = i >> 7, c = i & 127; int C = q * 128 + c;
            out[(size_t)(row0 + r) * DDIM + C] = sF[r * LDF + c] + b2[C];
        }
        __syncthreads();
    }
}

// ==== wmma node kernel (R13, unchanged) ====
__global__ void __launch_bounds__(NT, 2) node_kernel_w(
    int l, int use_agg, const float* __restrict__ cb1, const float* __restrict__ cb2) {
    extern __shared__ char smem[];
    __nv_bfloat16* sXh = (__nv_bfloat16*)smem;
    __nv_bfloat16* sXl = sXh + SM_XL;
    int tid = threadIdx.x;
    int wid = tid >> 5, mw = wid >> 2, nh = wid & 3;
    int row0 = blockIdx.x * TE;
    const size_t MM = (size_t)DDIM * DDIM;
    const __nv_bfloat16 *w1sh = d_w1h + (size_t)(l * 4 + 0) * MM, *w1sl = d_w1l + (size_t)(l * 4 + 0) * MM;
    const __nv_bfloat16 *w2sh = d_w2h + (size_t)(l * 4 + 0) * MM, *w2sl = d_w2l + (size_t)(l * 4 + 0) * MM;
    const __nv_bfloat16 *w1dh = d_w1h + (size_t)(l * 4 + 1) * MM, *w1dl = d_w1l + (size_t)(l * 4 + 1) * MM;
    const __nv_bfloat16 *w2dh = d_w2h + (size_t)(l * 4 + 1) * MM, *w2dl = d_w2l + (size_t)(l * 4 + 1) * MM;
    const float *b1s = cb1 + (l * 4 + 0) * DDIM, *b2s = cb2 + (l * 4 + 0) * DDIM;
    const float *b1d = cb1 + (l * 4 + 1) * DDIM, *b2d = cb2 + (l * 4 + 1) * DDIM;
    for (int i = tid; i < TE * DDIM; i += NT) {
        int r = i >> 8, c = i & 255;
        int row = row0 + r;
        float v = 0.0f;
        if (row < NATOMS) {
            size_t off = (size_t)row * DDIM + c;
            if (use_agg) { v = softplus_f(d_h[off] + d_agg[off]); d_h[off] = v; }
            else v = d_h[off];
            d_agg[off] = 0.0f;
        }
        __nv_bfloat16 h, lo; bsplit(v, h, lo);
        sXh[r * LDA + c] = h; sXl[r * LDA + c] = lo;
    }
    wmma::fragment<wmma::accumulator, 16, 16, 16, float> acc[8];
    wgemm(w1sh, w1sl, sXh, sXl, smem, acc, tid, mw, nh);
    for (int q = 0; q < 2; q++) {
        float* sF = stage_half(smem, acc, q, mw, nh);
        for (int i = tid; i < 64 * 128; i += NT) {
            int r = i >> 7, c = i & 127; int C = q * 128 + c;
            float v = mish_f(sF[r * LDF + c] + b1s[C]);
            __nv_bfloat16 h, lo; bsplit(v, h, lo);
            sXh[r * LDA + C] = h; sXl[r * LDA + C] = lo;
        }
        __syncthreads();
    }
    wgemm(w2sh, w2sl, sXh, sXl, smem, acc, tid, mw, nh);
    for (int q = 0; q < 2; q++) {
        float* sF = stage_half(smem, acc, q, mw, nh);
        for (int i = tid; i < 64 * 128; i += NT) {
            int r = i >> 7, c = i & 127; int C = q * 128 + c;
            int row = row0 + r;
            if (row < NATOMS) d_hsrc[(size_t)row * DDIM + C] = sF[r * LDF + c] + b2s[C];
        }
        __syncthreads();
    }
    for (int i = tid; i < TE * DDIM; i += NT) {
        int r = i >> 8, c = i & 255;
        int row = row0 + r;
        float v = (row < NATOMS) ? d_h[(size_t)row * DDIM + c] : 0.0f;
        __nv_bfloat16 h, lo; bsplit(v, h, lo);
        sXh[r * LDA + c] = h; sXl[r * LDA + c] = lo;
    }
    wgemm(w1dh, w1dl, sXh, sXl, smem, acc, tid, mw, nh);
    for (int q = 0; q < 2; q++) {
        float* sF = stage_half(smem, acc, q, mw, nh);
        for (int i = tid; i < 64 * 128; i += NT) {
            int r = i >> 7, c = i & 127; int C = q * 128 + c;
            float v = mish_f(sF[r * LDF + c] + b1d[C]);
            __nv_bfloat16 h, lo; bsplit(v, h, lo);
            sXh[r * LDA + C] = h; sXl[r * LDA + C] = lo;
        }
        __syncthreads();
    }
    wgemm(w2dh, w2dl, sXh, sXl, smem, acc, tid, mw, nh);
    for (int q = 0; q < 2; q++) {
        float* sF = stage_half(smem, acc, q, mw, nh);
        for (int i = tid; i < 64 * 128; i += NT) {
            int r = i >> 7, c = i & 127; int C = q * 128 + c;
            int row = row0 + r;
            if (row < NATOMS) d_hdst[(size_t)row * DDIM + C] = sF[r * LDF + c] + b2d[C];
        }
        __syncthreads();
    }
}

// ==== wmma edge kernel: interp e_lin + combine prologue -> m MLP -> scatter ====
__global__ void __launch_bounds__(NT, 2) edge_kernel_w(
    const int* __restrict__ esrc, const int* __restrict__ edst, int l,
    const float* __restrict__ cb1, const float* __restrict__ cb2) {
    extern __shared__ char smem[];
    __nv_bfloat16* sXh = (__nv_bfloat16*)smem;
    __nv_bfloat16* sXl = sXh + SM_XL;
    __shared__ int   sS[TE], sD[TE], sI[TE];
    __shared__ float sFr[TE];
    int tid = threadIdx.x;
    int wid = tid >> 5, mw = wid >> 2, nh = wid & 3;
    int e0 = blockIdx.x * TE;
    const size_t MM = (size_t)DDIM * DDIM;
    const __nv_bfloat16 *w1mh = d_w1h + (size_t)(l * 4 + 3) * MM, *w1ml = d_w1l + (size_t)(l * 4 + 3) * MM;
    const __nv_bfloat16 *w2mh = d_w2h + (size_t)(l * 4 + 3) * MM, *w2ml = d_w2l + (size_t)(l * 4 + 3) * MM;
    const float *b1m = cb1 + (l * 4 + 3) * DDIM, *b2m = cb2 + (l * 4 + 3) * DDIM;
    const float* tab = d_elin + (size_t)l * ELIN_N * DDIM;

    if (tid < TE) {
        int e = e0 + tid;
        sS[tid] = (e < NEDGES) ? esrc[e] : 0;
        sD[tid] = (e < NEDGES) ? edst[e] : 0;
        float d = (e < NEDGES) ? d_dist[e] : 0.0f;
        float x = d * ((float)(ELIN_N - 1) / ELIN_MAXD);
        if (x > (float)(ELIN_N - 2)) x = (float)(ELIN_N - 2);   // clamp (e_lin const beyond)
        int i0 = (int)x;
        sI[tid]  = i0;
        sFr[tid] = x - (float)i0;
    }
    __syncthreads();

    // combine prologue: hn = h_src*h_dst*COEF / lerp(e_lin)  -> X (bf16 split)
    for (int i = tid; i < TE * DDIM; i += NT) {
        int r = i >> 8, c = i & 255;
        const float* t0 = tab + (size_t)sI[r] * DDIM + c;
        float el = t0[0] + sFr[r] * (t0[DDIM] - t0[0]);
        float hn = d_hsrc[(size_t)sS[r] * DDIM + c] *
                   d_hdst[(size_t)sD[r] * DDIM + c] * COEF_F;
        float v = __fdividef(hn, el);
        __nv_bfloat16 h, lo; bsplit(v, h, lo);
        sXh[r * LDA + c] = h; sXl[r * LDA + c] = lo;
    }

    wmma::fragment<wmma::accumulator, 16, 16, 16, float> acc[8];

    // m MLP layer 1: mish -> X
    wgemm(w1mh, w1ml, sXh, sXl, smem, acc, tid, mw, nh);
    for (int q = 0; q < 2; q++) {
        float* sF = stage_half(smem, acc, q, mw, nh);
        for (int i = tid; i < 64 * 128; i += NT) {
            int r = i >> 7, c = i & 127; int C = q * 128 + c;
            float v = mish_f(sF[r * LDF + c] + b1m[C]);
            __nv_bfloat16 h, lo; bsplit(v, h, lo);
            sXh[r * LDA + C] = h; sXl[r * LDA + C] = lo;
        }
        __syncthreads();
    }

    // m MLP layer 2 + segment-sum scatter
    wgemm(w2mh, w2ml, sXh, sXl, smem, acc, tid, mw, nh);
    for (int q = 0; q < 2; q++) {
        float* sF = stage_half(smem, acc, q, mw, nh);
        for (int i = tid; i < 64 * 64; i += NT) {
            int r = i >> 6, c2 = i & 63; int C = q * 128 + 2 * c2;
            if (e0 + r < NEDGES) {
                float v0 = sF[r * LDF + 2 * c2]     + b2m[C];
                float v1 = sF[r * LDF + 2 * c2 + 1] + b2m[C + 1];
                red2(d_agg + (size_t)sD[r] * DDIM + C, v0, v1);
            }
        }
        __syncthreads();
    }
}

extern "C" void kernel_launch(void* const* d_in, const int* in_sizes, int n_in,
                              void* d_out, int out_size) {
    const int*   atom_types = (const int*)  d_in[0];
    const int*   esrc       = (const int*)  d_in[1];
    const int*   edst       = (const int*)  d_in[2];
    const int*   gids       = (const int*)  d_in[3];
    const float* r          = (const float*)d_in[4];
    const float* af         = (const float*)d_in[5];
    const float* emb_w      = (const float*)d_in[6];
    const float* emb_b      = (const float*)d_in[7];
    const float* cw1        = (const float*)d_in[8];
    const float* cb1        = (const float*)d_in[9];
    const float* cw2        = (const float*)d_in[10];
    const float* cb2        = (const float*)d_in[11];
    const float* out_w      = (const float*)d_in[12];
    const float* out_b      = (const float*)d_in[13];
    float* out = (float*)d_out;

    const int SMEM_EMBED = KEMB * EPADR * 4;
    cudaFuncSetAttribute(edge_kernel_w, cudaFuncAttributeMaxDynamicSharedMemorySize, SMEM_W);
    cudaFuncSetAttribute(node_kernel_w, cudaFuncAttributeMaxDynamicSharedMemorySize, SMEM_W);
    cudaFuncSetAttribute(elin_kernel,   cudaFuncAttributeMaxDynamicSharedMemorySize, SMEM_W);
    cudaFuncSetAttribute(embed_kernel,  cudaFuncAttributeMaxDynamicSharedMemorySize, SMEM_EMBED);

    dist_kernel<<<(NEDGES + 255) / 256, 256>>>(r);
    prep_w<<<(WELEMS + 255) / 256, 256>>>(cw1, cw2);
    embed_kernel<<<(NATOMS + ETE - 1) / ETE, ENT, SMEM_EMBED>>>(atom_types, af, emb_w, emb_b);
    for (int l = 0; l < LLAYERS; l++)
        elin_kernel<<<ELIN_N / TE, NT, SMEM_W>>>(l, cb1, cb2);

    for (int l = 0; l < LLAYERS; l++) {
        node_kernel_w<<<(NATOMS + TE - 1) / TE, NT, SMEM_W>>>(l, l > 0 ? 1 : 0, cb1, cb2);
        edge_kernel_w<<<(NEDGES + TE - 1) / TE, NT, SMEM_W>>>(esrc, edst, l, cb1, cb2);
    }

    zero_pool_kernel<<<(NGRAPH + 255) / 256, 256>>>();
    pool_kernel<<<(NATOMS * 32 + 255) / 256, 256>>>(gids, out_w);
    final_kernel<<<(NGRAPH + 255) / 256, 256>>>(out_b, out);
}

// round 17
// speedup vs baseline: 1.9506x; 1.0129x over previous
#include <cuda_runtime.h>
#include <cuda_bf16.h>
#include <mma.h>
#include <math.h>

using namespace nvcuda;

#define NATOMS 25000
#define NEDGES 300000
#define NGRAPH 500
#define DDIM   256
#define ADIM   200
#define LLAYERS 3
#define TE     64
#define NT     256
#define LDA    264
#define LDB    264
#define LDF    132
#define KCH    16
#define NCH    (DDIM / KCH)
#define ELIN_N    8192
#define ELIN_BLKS (ELIN_N / TE)
#define ELIN_MAXD 2.0f

#define COEF_F ((float)(1.602176634e-19 * 1.602176634e-19 / \
                 (4.0 * 3.14159265358979323846 * 8.8541878128e-12 * 1e-10)))

typedef unsigned long long u64;

#define SM_XL   (64 * LDA)
#define SM_BOFF (2 * SM_XL * 2)
#define SM_BSTG (2 * KCH * LDB * 2)
#define SMEM_W  (SM_BOFF + 2 * SM_BSTG)     // 101,376 bytes

// ---- scratch ----
__device__ float d_dist[NEDGES];
__device__ float d_h   [NATOMS * DDIM];
__device__ float d_hsrc[NATOMS * DDIM];
__device__ float d_hdst[NATOMS * DDIM];
__device__ float d_agg [NATOMS * DDIM];
__device__ float d_pool[NGRAPH];
__device__ int   d_cnt [NGRAPH];
__device__ float d_elin[LLAYERS * ELIN_N * DDIM];

#define WELEMS (LLAYERS * 4 * DDIM * DDIM)
__device__ __align__(256) __nv_bfloat16 d_w1h[WELEMS];
__device__ __align__(256) __nv_bfloat16 d_w1l[WELEMS];
__device__ __align__(256) __nv_bfloat16 d_w2h[WELEMS];
__device__ __align__(256) __nv_bfloat16 d_w2l[WELEMS];

// ---- helpers ----
__device__ __forceinline__ void bsplit(float v, __nv_bfloat16& h, __nv_bfloat16& l) {
    h = __float2bfloat16(v);
    l = __float2bfloat16(v - __bfloat162float(h));
}
__device__ __forceinline__ void red2(float* p, float a, float b) {
    asm volatile("red.global.add.v2.f32 [%0], {%1, %2};" :: "l"(p), "f"(a), "f"(b) : "memory");
}
__device__ __forceinline__ float softplus_f(float x) {
    return fmaxf(x, 0.0f) + __logf(1.0f + __expf(-fabsf(x)));
}
__device__ __forceinline__ float mish_f(float x) {
    float ex = __expf(fminf(x, 20.0f));
    float p  = 1.0f + ex;
    float p2 = p * p;
    return x * __fdividef(p2 - 1.0f, p2 + 1.0f);
}
__device__ __forceinline__ void cpa16(unsigned saddr, const void* gptr) {
    asm volatile("cp.async.cg.shared.global [%0], [%1], 16;" :: "r"(saddr), "l"(gptr));
}
#define CP_COMMIT() asm volatile("cp.async.commit_group;" ::: "memory")
__device__ __forceinline__ void cp_wait1() { asm volatile("cp.async.wait_group 1;" ::: "memory"); }
__device__ __forceinline__ void cp_wait0() { asm volatile("cp.async.wait_group 0;" ::: "memory"); }

// ---- weight prep ----
__global__ void __launch_bounds__(256) prep_w(const float* __restrict__ cw1,
                                              const float* __restrict__ cw2) {
    int i = blockIdx.x * blockDim.x + threadIdx.x;
    if (i < WELEMS) {
        __nv_bfloat16 h, l;
        bsplit(cw1[i], h, l); d_w1h[i] = h; d_w1l[i] = l;
        bsplit(cw2[i], h, l); d_w2h[i] = h; d_w2l[i] = l;
    }
}

// ---- wmma GEMM (2M x 4N warp map; dependency-broken mma ordering) ----
__device__ __forceinline__ void ldB_async(unsigned sB, const __nv_bfloat16* __restrict__ gWh,
                                          const __nv_bfloat16* __restrict__ gWl,
                                          int k0, int tid) {
    int rr = tid >> 4;
    int cb = (tid & 15) * 16;
    unsigned dsth = sB + (unsigned)(rr * LDB + cb) * 2;
    unsigned dstl = dsth + KCH * LDB * 2;
    const __nv_bfloat16* sh = gWh + (size_t)(k0 + rr) * DDIM + cb;
    const __nv_bfloat16* sl = gWl + (size_t)(k0 + rr) * DDIM + cb;
    cpa16(dsth, sh);      cpa16(dsth + 16, sh + 8);
    cpa16(dstl, sl);      cpa16(dstl + 16, sl + 8);
}
__device__ __forceinline__ void wgemm(
    const __nv_bfloat16* __restrict__ gWh, const __nv_bfloat16* __restrict__ gWl,
    const __nv_bfloat16* sXh, const __nv_bfloat16* sXl, char* smem,
    wmma::fragment<wmma::accumulator, 16, 16, 16, float>* acc,
    int tid, int mw, int nh) {
#pragma unroll
    for (int f = 0; f < 8; f++) wmma::fill_fragment(acc[f], 0.0f);
    __nv_bfloat16* sB0 = (__nv_bfloat16*)(smem + SM_BOFF);
    __nv_bfloat16* sB1 = (__nv_bfloat16*)(smem + SM_BOFF + SM_BSTG);
    unsigned a0 = (unsigned)__cvta_generic_to_shared(sB0);
    unsigned a1 = (unsigned)__cvta_generic_to_shared(sB1);
    ldB_async(a0, gWh, gWl, 0, tid);
    CP_COMMIT();
    for (int c = 0; c < NCH; c++) {
        __syncthreads();
        if (c < NCH - 1) ldB_async((c & 1) ? a0 : a1, gWh, gWl, (c + 1) * KCH, tid);
        CP_COMMIT();
        if (c < NCH - 1) cp_wait1(); else cp_wait0();
        __syncthreads();
        const __nv_bfloat16* bh_base = (c & 1) ? sB1 : sB0;
        const __nv_bfloat16* bl_base = bh_base + KCH * LDB;
        wmma::fragment<wmma::matrix_a, 16, 16, 16, __nv_bfloat16, wmma::row_major> ah[2], al[2];
        wmma::fragment<wmma::matrix_b, 16, 16, 16, __nv_bfloat16, wmma::row_major> bh[4], bl[4];
#pragma unroll
        for (int fm = 0; fm < 2; fm++) {
            wmma::load_matrix_sync(ah[fm], sXh + (mw * 32 + fm * 16) * LDA + c * KCH, LDA);
            wmma::load_matrix_sync(al[fm], sXl + (mw * 32 + fm * 16) * LDA + c * KCH, LDA);
        }
#pragma unroll
        for (int fn = 0; fn < 4; fn++)
            wmma::load_matrix_sync(bh[fn], bh_base + nh * 64 + fn * 16, LDB);
        // pass 1: Xh * Wh  (8 independent accumulators back-to-back)
#pragma unroll
        for (int fn = 0; fn < 4; fn++)
#pragma unroll
            for (int fm = 0; fm < 2; fm++)
                wmma::mma_sync(acc[fm * 4 + fn], ah[fm], bh[fn], acc[fm * 4 + fn]);
        // pass 2: Xl * Wh
#pragma unroll
        for (int fn = 0; fn < 4; fn++)
#pragma unroll
            for (int fm = 0; fm < 2; fm++)
                wmma::mma_sync(acc[fm * 4 + fn], al[fm], bh[fn], acc[fm * 4 + fn]);
#pragma unroll
        for (int fn = 0; fn < 4; fn++)
            wmma::load_matrix_sync(bl[fn], bl_base + nh * 64 + fn * 16, LDB);
        // pass 3: Xh * Wl
#pragma unroll
        for (int fn = 0; fn < 4; fn++)
#pragma unroll
            for (int fm = 0; fm < 2; fm++)
                wmma::mma_sync(acc[fm * 4 + fn], ah[fm], bl[fn], acc[fm * 4 + fn]);
    }
    __syncthreads();
}
__device__ __forceinline__ float* stage_half(
    char* smem, wmma::fragment<wmma::accumulator, 16, 16, 16, float>* acc,
    int q, int mw, int nh) {
    float* sF = (float*)(smem + SM_BOFF);
    if ((nh >> 1) == q) {
#pragma unroll
        for (int fm = 0; fm < 2; fm++)
#pragma unroll
            for (int fn = 0; fn < 4; fn++)
                wmma::store_matrix_sync(sF + (mw * 32 + fm * 16) * LDF + (nh & 1) * 64 + fn * 16,
                                        acc[fm * 4 + fn], LDF, wmma::mem_row_major);
    }
    __syncthreads();
    return sF;
}

// ---- small kernels ----
__global__ void __launch_bounds__(256) dist_kernel(const float* __restrict__ r) {
    int e = blockIdx.x * blockDim.x + threadIdx.x;
    if (e < NEDGES) {
        float x = r[3 * e], y = r[3 * e + 1], z = r[3 * e + 2];
        d_dist[e] = sqrtf(x * x + y * y + z * z);
    }
}
__global__ void __launch_bounds__(256) zero_pool_kernel() {
    int g = blockIdx.x * blockDim.x + threadIdx.x;
    if (g < NGRAPH) { d_pool[g] = 0.0f; d_cnt[g] = 0; }
}
__global__ void __launch_bounds__(256) pool_kernel(const int* __restrict__ gids,
                                                   const float* __restrict__ out_w) {
    int warp = (blockIdx.x * blockDim.x + threadIdx.x) >> 5;
    int lane = threadIdx.x & 31;
    if (warp >= NATOMS) return;
    float s = 0.0f;
    for (int k = lane; k < DDIM; k += 32) {
        size_t off = (size_t)warp * DDIM + k;
        s += softplus_f(d_h[off] + d_agg[off]) * out_w[k];
    }
#pragma unroll
    for (int off = 16; off > 0; off >>= 1)
        s += __shfl_xor_sync(0xFFFFFFFFu, s, off);
    if (lane == 0) {
        atomicAdd(&d_pool[gids[warp]], s);
        atomicAdd(&d_cnt[gids[warp]], 1);
    }
}
__global__ void __launch_bounds__(256) final_kernel(const float* __restrict__ out_b,
                                                    float* __restrict__ out) {
    int g = blockIdx.x * blockDim.x + threadIdx.x;
    if (g < NGRAPH)
        out[g] = d_pool[g] / fmaxf((float)d_cnt[g], 1.0f) + out_b[0];
}

// ==== scalar embed (unchanged) ====
#define ETE   32
#define ENT   128
#define EPADR 36
#define KEMB  224
__device__ __forceinline__ u64 pack2f(float lo, float hi) {
    u64 v; asm("mov.b64 %0, {%1, %2};" : "=l"(v) : "f"(lo), "f"(hi)); return v;
}
__device__ __forceinline__ void unpack2f(u64 v, float& lo, float& hi) {
    asm("mov.b64 {%0, %1}, %2;" : "=f"(lo), "=f"(hi) : "l"(v));
}
__device__ __forceinline__ void fma2(u64& a, u64 x, u64 w) {
    asm("fma.rn.f32x2 %0, %1, %2, %0;" : "+l"(a) : "l"(x), "l"(w));
}
__device__ __forceinline__ void eldw4c(float2 w[4][2], const float* __restrict__ W,
                                       int k, int cp, int kmax) {
#pragma unroll
    for (int i = 0; i < 4; i++) {
        int kk = k + i; if (kk >= kmax) kk = kmax - 1;
        w[i][0] = *(const float2*)(W + (size_t)kk * DDIM + 2 * cp);
        w[i][1] = *(const float2*)(W + (size_t)kk * DDIM + 2 * cp + 128);
    }
}
__device__ __forceinline__ void eldx(ulonglong2 cur[4], const float* __restrict__ xs, int k) {
    const ulonglong2* xr = (const ulonglong2*)(xs + (size_t)k * EPADR);
#pragma unroll
    for (int j = 0; j < 4; j++) cur[j] = xr[j];
}
__device__ __forceinline__ void efma_k(u64 acc[32], float2 w01, float2 w23,
                                       const ulonglong2 cur[4]) {
    u64 wv0 = pack2f(w01.x, w01.x), wv1 = pack2f(w01.y, w01.y);
    u64 wv2 = pack2f(w23.x, w23.x), wv3 = pack2f(w23.y, w23.y);
#pragma unroll
    for (int j2 = 0; j2 < 4; j2++) {
        u64 plo = cur[j2].x, phi = cur[j2].y;
        fma2(acc[     2 * j2], plo, wv0); fma2(acc[     2 * j2 + 1], phi, wv0);
        fma2(acc[ 8 + 2 * j2], plo, wv1); fma2(acc[ 8 + 2 * j2 + 1], phi, wv1);
        fma2(acc[16 + 2 * j2], plo, wv2); fma2(acc[16 + 2 * j2 + 1], phi, wv2);
        fma2(acc[24 + 2 * j2], plo, wv3); fma2(acc[24 + 2 * j2 + 1], phi, wv3);
    }
}
__global__ void __launch_bounds__(ENT) embed_kernel(const int* __restrict__ atom_types,
                                                    const float* __restrict__ af,
                                                    const float* __restrict__ emb_w,
                                                    const float* __restrict__ emb_b) {
    extern __shared__ float esm[];
    float* xa = esm;
    __shared__ int sT[ETE];
    int tid = threadIdx.x;
    int cp = tid & 63, rg = tid >> 6, rbase = rg * 16;
    int row0 = blockIdx.x * ETE;
    if (tid < ETE) {
        int row = row0 + tid;
        sT[tid] = (row < NATOMS) ? atom_types[row] : 0;
    }
    __syncthreads();
    for (int idx = tid; idx < ETE * KEMB; idx += ENT) {
        int r = idx / KEMB, k = idx - r * KEMB;
        float v = 0.0f;
        if (k < ADIM && row0 + r < NATOMS) v = af[(size_t)sT[r] * ADIM + k];
        xa[k * EPADR + r] = v;
    }
    __syncthreads();
    u64 acc[32];
#pragma unroll
    for (int j = 0; j < 32; j++) acc[j] = 0ULL;
    {
        const float* xs = xa + rbase;
        float2 wa[4][2], wb[4][2];
        ulonglong2 cur[4], nxt[4];
        eldw4c(wa, emb_w, 0, cp, ADIM);
        eldx(cur, xs, 0);
        for (int k0 = 0; k0 < KEMB; k0 += 8) {
            eldw4c(wb, emb_w, k0 + 4, cp, ADIM);
#pragma unroll
            for (int i = 0; i < 4; i++) {
                int kk = k0 + i + 1; if (kk >= KEMB) kk = 0;
                eldx(nxt, xs, kk);
                efma_k(acc, wa[i][0], wa[i][1], cur);
#pragma unroll
                for (int j = 0; j < 4; j++) cur[j] = nxt[j];
            }
            eldw4c(wa, emb_w, (k0 + 8 < KEMB) ? k0 + 8 : 0, cp, ADIM);
#pragma unroll
            for (int i = 0; i < 4; i++) {
                int kk = k0 + 5 + i; if (kk >= KEMB) kk = 0;
                eldx(nxt, xs, kk);
                efma_k(acc, wb[i][0], wb[i][1], cur);
#pragma unroll
                for (int j = 0; j < 4; j++) cur[j] = nxt[j];
            }
        }
    }
    float2 b01 = *(const float2*)(emb_b + 2 * cp);
    float2 b23 = *(const float2*)(emb_b + 2 * cp + 128);
#pragma unroll
    for (int j = 0; j < 8; j++) {
        float lo0, hi0, lo1, hi1, lo2, hi2, lo3, hi3;
        unpack2f(acc[j],      lo0, hi0);
        unpack2f(acc[8 + j],  lo1, hi1);
        unpack2f(acc[16 + j], lo2, hi2);
        unpack2f(acc[24 + j], lo3, hi3);
        int r0 = row0 + rbase + 2 * j, r1 = r0 + 1;
        if (r0 < NATOMS) {
            *(float2*)(d_h + (size_t)r0 * DDIM + 2 * cp)       = make_float2(lo0 + b01.x, lo1 + b01.y);
            *(float2*)(d_h + (size_t)r0 * DDIM + 2 * cp + 128) = make_float2(lo2 + b23.x, lo3 + b23.y);
        }
        if (r1 < NATOMS) {
            *(float2*)(d_h + (size_t)r1 * DDIM + 2 * cp)       = make_float2(hi0 + b01.x, hi1 + b01.y);
            *(float2*)(d_h + (size_t)r1 * DDIM + 2 * cp + 128) = make_float2(hi2 + b23.x, hi3 + b23.y);
        }
    }
}

// ==== e_lin table build (all layers in one launch) ====
__global__ void __launch_bounds__(NT, 2) elin_kernel(
    const float* __restrict__ cb1, const float* __restrict__ cb2) {
    extern __shared__ char smem[];
    __nv_bfloat16* sXh = (__nv_bfloat16*)smem;
    __nv_bfloat16* sXl = sXh + SM_XL;
    int tid = threadIdx.x;
    int wid = tid >> 5, mw = wid >> 2, nh = wid & 3;
    int l    = blockIdx.x / ELIN_BLKS;
    int row0 = (blockIdx.x % ELIN_BLKS) * TE;
    const size_t MM = (size_t)DDIM * DDIM;
    const __nv_bfloat16 *w1h = d_w1h + (size_t)(l * 4 + 2) * MM, *w1l = d_w1l + (size_t)(l * 4 + 2) * MM;
    const __nv_bfloat16 *w2h = d_w2h + (size_t)(l * 4 + 2) * MM, *w2l = d_w2l + (size_t)(l * 4 + 2) * MM;
    const float *b1 = cb1 + (l * 4 + 2) * DDIM, *b2 = cb2 + (l * 4 + 2) * DDIM;
    const float step = ELIN_MAXD / (float)(ELIN_N - 1);

    for (int i = tid; i < TE * DDIM; i += NT) {
        int r = i >> 8, c = i & 255;
        float d = (float)(row0 + r) * step;
        float t = d - (float)c * (1.0f / 255.0f);
        float v = __expf(-255.0f * t * t);
        __nv_bfloat16 h, lo; bsplit(v, h, lo);
        sXh[r * LDA + c] = h; sXl[r * LDA + c] = lo;
    }
    wmma::fragment<wmma::accumulator, 16, 16, 16, float> acc[8];
    wgemm(w1h, w1l, sXh, sXl, smem, acc, tid, mw, nh);
    for (int q = 0; q < 2; q++) {
        float* sF = stage_half(smem, acc, q, mw, nh);
        for (int i = tid; i < 64 * 128; i += NT) {
            int r = i >> 7, c = i & 127; int C = q * 128 + c;
            float v = mish_f(sF[r * LDF + c] + b1[C]);
            __nv_bfloat16 h, lo; bsplit(v, h, lo);
            sXh[r * LDA + C] = h; sXl[r * LDA + C] = lo;
        }
        __syncthreads();
    }
    wgemm(w2h, w2l, sXh, sXl, smem, acc, tid, mw, nh);
    float* out = d_elin + (size_t)l * ELIN_N * DDIM;
    for (int q = 0; q < 2; q++) {
        float* sF = stage_half(smem, acc, q, mw, nh);
        for (int i = tid; i < 64 * 128; i += NT) {
            int r = i >> 7, c = i & 127; int C = q * 128 + c;
            out[(size_t)(row0 + r) * DDIM + C] = sF[r * LDF + c] + b2[C];
        }
        __syncthreads();
    }
}

// ==== wmma node kernel ====
__global__ void __launch_bounds__(NT, 2) node_kernel_w(
    int l, int use_agg, const float* __restrict__ cb1, const float* __restrict__ cb2) {
    extern __shared__ char smem[];
    __nv_bfloat16* sXh = (__nv_bfloat16*)smem;
    __nv_bfloat16* sXl = sXh + SM_XL;
    int tid = threadIdx.x;
    int wid = tid >> 5, mw = wid >> 2, nh = wid & 3;
    int row0 = blockIdx.x * TE;
    const size_t MM = (size_t)DDIM * DDIM;
    const __nv_bfloat16 *w1sh = d_w1h + (size_t)(l * 4 + 0) * MM, *w1sl = d_w1l + (size_t)(l * 4 + 0) * MM;
    const __nv_bfloat16 *w2sh = d_w2h + (size_t)(l * 4 + 0) * MM, *w2sl = d_w2l + (size_t)(l * 4 + 0) * MM;
    const __nv_bfloat16 *w1dh = d_w1h + (size_t)(l * 4 + 1) * MM, *w1dl = d_w1l + (size_t)(l * 4 + 1) * MM;
    const __nv_bfloat16 *w2dh = d_w2h + (size_t)(l * 4 + 1) * MM, *w2dl = d_w2l + (size_t)(l * 4 + 1) * MM;
    const float *b1s = cb1 + (l * 4 + 0) * DDIM, *b2s = cb2 + (l * 4 + 0) * DDIM;
    const float *b1d = cb1 + (l * 4 + 1) * DDIM, *b2d = cb2 + (l * 4 + 1) * DDIM;
    for (int i = tid; i < TE * DDIM; i += NT) {
        int r = i >> 8, c = i & 255;
        int row = row0 + r;
        float v = 0.0f;
        if (row < NATOMS) {
            size_t off = (size_t)row * DDIM + c;
            if (use_agg) { v = softplus_f(d_h[off] + d_agg[off]); d_h[off] = v; }
            else v = d_h[off];
            d_agg[off] = 0.0f;
        }
        __nv_bfloat16 h, lo; bsplit(v, h, lo);
        sXh[r * LDA + c] = h; sXl[r * LDA + c] = lo;
    }
    wmma::fragment<wmma::accumulator, 16, 16, 16, float> acc[8];
    wgemm(w1sh, w1sl, sXh, sXl, smem, acc, tid, mw, nh);
    for (int q = 0; q < 2; q++) {
        float* sF = stage_half(smem, acc, q, mw, nh);
        for (int i = tid; i < 64 * 128; i += NT) {
            int r = i >> 7, c = i & 127; int C = q * 128 + c;
            float v = mish_f(sF[r * LDF + c] + b1s[C]);
            __nv_bfloat16 h, lo; bsplit(v, h, lo);
            sXh[r * LDA + C] = h; sXl[r * LDA + C] = lo;
        }
        __syncthreads();
    }
    wgemm(w2sh, w2sl, sXh, sXl, smem, acc, tid, mw, nh);
    for (int q = 0; q < 2; q++) {
        float* sF = stage_half(smem, acc, q, mw, nh);
        for (int i = tid; i < 64 * 128; i += NT) {
            int r = i >> 7, c = i & 127; int C = q * 128 + c;
            int row = row0 + r;
            if (row < NATOMS) d_hsrc[(size_t)row * DDIM + C] = sF[r * LDF + c] + b2s[C];
        }
        __syncthreads();
    }
    for (int i = tid; i < TE * DDIM; i += NT) {
        int r = i >> 8, c = i & 255;
        int row = row0 + r;
        float v = (row < NATOMS) ? d_h[(size_t)row * DDIM + c] : 0.0f;
        __nv_bfloat16 h, lo; bsplit(v, h, lo);
        sXh[r * LDA + c] = h; sXl[r * LDA + c] = lo;
    }
    wgemm(w1dh, w1dl, sXh, sXl, smem, acc, tid, mw, nh);
    for (int q = 0; q < 2; q++) {
        float* sF = stage_half(smem, acc, q, mw, nh);
        for (int i = tid; i < 64 * 128; i += NT) {
            int r = i >> 7, c = i & 127; int C = q * 128 + c;
            float v = mish_f(sF[r * LDF + c] + b1d[C]);
            __nv_bfloat16 h, lo; bsplit(v, h, lo);
            sXh[r * LDA + C] = h; sXl[r * LDA + C] = lo;
        }
        __syncthreads();
    }
    wgemm(w2dh, w2dl, sXh, sXl, smem, acc, tid, mw, nh);
    for (int q = 0; q < 2; q++) {
        float* sF = stage_half(smem, acc, q, mw, nh);
        for (int i = tid; i < 64 * 128; i += NT) {
            int r = i >> 7, c = i & 127; int C = q * 128 + c;
            int row = row0 + r;
            if (row < NATOMS) d_hdst[(size_t)row * DDIM + C] = sF[r * LDF + c] + b2d[C];
        }
        __syncthreads();
    }
}

// ==== wmma edge kernel: interp e_lin + combine -> m MLP -> scatter ====
__global__ void __launch_bounds__(NT, 2) edge_kernel_w(
    const int* __restrict__ esrc, const int* __restrict__ edst, int l,
    const float* __restrict__ cb1, const float* __restrict__ cb2) {
    extern __shared__ char smem[];
    __nv_bfloat16* sXh = (__nv_bfloat16*)smem;
    __nv_bfloat16* sXl = sXh + SM_XL;
    __shared__ int   sS[TE], sD[TE], sI[TE];
    __shared__ float sFr[TE];
    int tid = threadIdx.x;
    int wid = tid >> 5, mw = wid >> 2, nh = wid & 3;
    int e0 = blockIdx.x * TE;
    const size_t MM = (size_t)DDIM * DDIM;
    const __nv_bfloat16 *w1mh = d_w1h + (size_t)(l * 4 + 3) * MM, *w1ml = d_w1l + (size_t)(l * 4 + 3) * MM;
    const __nv_bfloat16 *w2mh = d_w2h + (size_t)(l * 4 + 3) * MM, *w2ml = d_w2l + (size_t)(l * 4 + 3) * MM;
    const float *b1m = cb1 + (l * 4 + 3) * DDIM, *b2m = cb2 + (l * 4 + 3) * DDIM;
    const float* tab = d_elin + (size_t)l * ELIN_N * DDIM;

    if (tid < TE) {
        int e = e0 + tid;
        sS[tid] = (e < NEDGES) ? esrc[e] : 0;
        sD[tid] = (e < NEDGES) ? edst[e] : 0;
        float d = (e < NEDGES) ? d_dist[e] : 0.0f;
        float x = d * ((float)(ELIN_N - 1) / ELIN_MAXD);
        if (x > (float)(ELIN_N - 2)) x = (float)(ELIN_N - 2);
        int i0 = (int)x;
        sI[tid]  = i0;
        sFr[tid] = x - (float)i0;
    }
    __syncthreads();

    for (int i = tid; i < TE * DDIM; i += NT) {
        int r = i >> 8, c = i & 255;
        const float* t0 = tab + (size_t)sI[r] * DDIM + c;
        float el = t0[0] + sFr[r] * (t0[DDIM] - t0[0]);
        float hn = d_hsrc[(size_t)sS[r] * DDIM + c] *
                   d_hdst[(size_t)sD[r] * DDIM + c] * COEF_F;
        float v = __fdividef(hn, el);
        __nv_bfloat16 h, lo; bsplit(v, h, lo);
        sXh[r * LDA + c] = h; sXl[r * LDA + c] = lo;
    }

    wmma::fragment<wmma::accumulator, 16, 16, 16, float> acc[8];

    wgemm(w1mh, w1ml, sXh, sXl, smem, acc, tid, mw, nh);
    for (int q = 0; q < 2; q++) {
        float* sF = stage_half(smem, acc, q, mw, nh);
        for (int i = tid; i < 64 * 128; i += NT) {
            int r = i >> 7, c = i & 127; int C = q * 128 + c;
            float v = mish_f(sF[r * LDF + c] + b1m[C]);
            __nv_bfloat16 h, lo; bsplit(v, h, lo);
            sXh[r * LDA + C] = h; sXl[r * LDA + C] = lo;
        }
        __syncthreads();
    }

    wgemm(w2mh, w2ml, sXh, sXl, smem, acc, tid, mw, nh);
    for (int q = 0; q < 2; q++) {
        float* sF = stage_half(smem, acc, q, mw, nh);
        for (int i = tid; i < 64 * 64; i += NT) {
            int r = i >> 6, c2 = i & 63; int C = q * 128 + 2 * c2;
            if (e0 + r < NEDGES) {
                float v0 = sF[r * LDF + 2 * c2]     + b2m[C];
                float v1 = sF[r * LDF + 2 * c2 + 1] + b2m[C + 1];
                red2(d_agg + (size_t)sD[r] * DDIM + C, v0, v1);
            }
        }
        __syncthreads();
    }
}

extern "C" void kernel_launch(void* const* d_in, const int* in_sizes, int n_in,
                              void* d_out, int out_size) {
    const int*   atom_types = (const int*)  d_in[0];
    const int*   esrc       = (const int*)  d_in[1];
    const int*   edst       = (const int*)  d_in[2];
    const int*   gids       = (const int*)  d_in[3];
    const float* r          = (const float*)d_in[4];
    const float* af         = (const float*)d_in[5];
    const float* emb_w      = (const float*)d_in[6];
    const float* emb_b      = (const float*)d_in[7];
    const float* cw1        = (const float*)d_in[8];
    const float* cb1        = (const float*)d_in[9];
    const float* cw2        = (const float*)d_in[10];
    const float* cb2        = (const float*)d_in[11];
    const float* out_w      = (const float*)d_in[12];
    const float* out_b      = (const float*)d_in[13];
    float* out = (float*)d_out;

    const int SMEM_EMBED = KEMB * EPADR * 4;
    cudaFuncSetAttribute(edge_kernel_w, cudaFuncAttributeMaxDynamicSharedMemorySize, SMEM_W);
    cudaFuncSetAttribute(node_kernel_w, cudaFuncAttributeMaxDynamicSharedMemorySize, SMEM_W);
    cudaFuncSetAttribute(elin_kernel,   cudaFuncAttributeMaxDynamicSharedMemorySize, SMEM_W);
    cudaFuncSetAttribute(embed_kernel,  cudaFuncAttributeMaxDynamicSharedMemorySize, SMEM_EMBED);

    dist_kernel<<<(NEDGES + 255) / 256, 256>>>(r);
    prep_w<<<(WELEMS + 255) / 256, 256>>>(cw1, cw2);
    embed_kernel<<<(NATOMS + ETE - 1) / ETE, ENT, SMEM_EMBED>>>(atom_types, af, emb_w, emb_b);
    elin_kernel<<<LLAYERS * ELIN_BLKS, NT, SMEM_W>>>(cb1, cb2);

    for (int l = 0; l < LLAYERS; l++) {
        node_kernel_w<<<(NATOMS + TE - 1) / TE, NT, SMEM_W>>>(l, l > 0 ? 1 : 0, cb1, cb2);
        edge_kernel_w<<<(NEDGES + TE - 1) / TE, NT, SMEM_W>>>(esrc, edst, l, cb1, cb2);
    }

    zero_pool_kernel<<<(NGRAPH + 255) / 256, 256>>>();
    pool_kernel<<<(NATOMS * 32 + 255) / 256, 256>>>(gids, out_w);
    final_kernel<<<(NGRAPH + 255) / 256, 256>>>(out_b, out);
}